// round 15
// baseline (speedup 1.0000x reference)
#include <cuda_runtime.h>
#include <cuda_bf16.h>
#include <stdint.h>
#include <math.h>

#define HIDDEN 2048
#define NHEADS 16
#define NKV 4
#define HD 128
#define SEQ 2048
#define BATCH 2
#define MROWS (BATCH * SEQ)   // 4096
#define KVW (NKV * HD)        // 512
#define KDIM 2048
// 1/sqrt(128) * log2(e)  (exp2-based softmax)
#define QSCALE_L2E 0.1275174500772518f

// ---------------- scratch (no allocations allowed) ----------------
__device__ __align__(128) float2 g_rope[SEQ * 64];
__device__ __align__(128) __nv_bfloat16 g_xhi[MROWS * KDIM];
__device__ __align__(128) __nv_bfloat16 g_xlo[MROWS * KDIM];
__device__ __align__(128) __nv_bfloat16 g_qhi[MROWS * HIDDEN];
__device__ __align__(128) __nv_bfloat16 g_qlo[MROWS * HIDDEN];
__device__ __align__(128) __nv_bfloat16 g_ahi[MROWS * KDIM];
__device__ __align__(128) __nv_bfloat16 g_alo[MROWS * KDIM];
__device__ __align__(128) __nv_bfloat16 g_khi[MROWS * KVW];
__device__ __align__(128) __nv_bfloat16 g_klo[MROWS * KVW];
__device__ __align__(128) __nv_bfloat16 g_vhi[MROWS * KVW];
__device__ __align__(128) __nv_bfloat16 g_vlo[MROWS * KVW];
__device__ __align__(128) __nv_bfloat16 g_wqhi[HIDDEN * KDIM];  // transposed [N][K], rope-permuted
__device__ __align__(128) __nv_bfloat16 g_wqlo[HIDDEN * KDIM];
__device__ __align__(128) __nv_bfloat16 g_wkhi[KVW * KDIM];     // rope-permuted
__device__ __align__(128) __nv_bfloat16 g_wklo[KVW * KDIM];
__device__ __align__(128) __nv_bfloat16 g_wvhi[KVW * KDIM];
__device__ __align__(128) __nv_bfloat16 g_wvlo[KVW * KDIM];
__device__ __align__(128) __nv_bfloat16 g_wohi[HIDDEN * KDIM];
__device__ __align__(128) __nv_bfloat16 g_wolo[HIDDEN * KDIM];

// ================= helpers =================
__device__ __forceinline__ uint32_t smem_u32(const void* p) {
    uint32_t a;
    asm("{ .reg .u64 t; cvta.to.shared.u64 t, %1; cvt.u32.u64 %0, t; }"
        : "=r"(a) : "l"(p));
    return a;
}
#define CP_ASYNC16(dst, src) \
    asm volatile("cp.async.cg.shared.global [%0], [%1], 16;" :: "r"(dst), "l"(src) : "memory")
#define CP_COMMIT() asm volatile("cp.async.commit_group;" ::: "memory")
#define CP_WAIT1()  asm volatile("cp.async.wait_group 1;" ::: "memory")
#define CP_WAIT0()  asm volatile("cp.async.wait_group 0;" ::: "memory")

__device__ __forceinline__ void ldsm_x4(uint32_t* r, uint32_t addr) {
    asm volatile("ldmatrix.sync.aligned.m8n8.x4.shared.b16 {%0,%1,%2,%3}, [%4];"
                 : "=r"(r[0]), "=r"(r[1]), "=r"(r[2]), "=r"(r[3]) : "r"(addr));
}
__device__ __forceinline__ void ldsm_x4_t(uint32_t* r, uint32_t addr) {
    asm volatile("ldmatrix.sync.aligned.m8n8.x4.trans.shared.b16 {%0,%1,%2,%3}, [%4];"
                 : "=r"(r[0]), "=r"(r[1]), "=r"(r[2]), "=r"(r[3]) : "r"(addr));
}
__device__ __forceinline__ void mma16816(float* d, const uint32_t* a, const uint32_t* b) {
    asm volatile("mma.sync.aligned.m16n8k16.row.col.f32.bf16.bf16.f32 "
                 "{%0,%1,%2,%3}, {%4,%5,%6,%7}, {%8,%9}, {%0,%1,%2,%3};"
                 : "+f"(d[0]), "+f"(d[1]), "+f"(d[2]), "+f"(d[3])
                 : "r"(a[0]), "r"(a[1]), "r"(a[2]), "r"(a[3]), "r"(b[0]), "r"(b[1]));
}
__device__ __forceinline__ uint32_t packbf(float x, float y) {
    __nv_bfloat162 t;
    t.x = __float2bfloat16_rn(x);
    t.y = __float2bfloat16_rn(y);
    return *(uint32_t*)&t;
}
__device__ __forceinline__ float fexp2(float x) {
    float y;
    asm("ex2.approx.f32 %0, %1;" : "=f"(y) : "f"(x));
    return y;
}

// ================= RoPE cos/sin table =================
__global__ void rope_table(float2* __restrict__ tab)
{
    int idx = blockIdx.x * blockDim.x + threadIdx.x;   // SEQ*64
    int s = idx >> 6;
    int d = idx & 63;
    float inv = exp2f(-(float)d * (13.287712379549449f / 64.0f));
    float ang = (float)s * inv;
    float sn, cs;
    sincosf(ang, &sn, &cs);
    tab[idx] = make_float2(cs, sn);
}

// ================= fp32 -> bf16 hi/lo split =================
__global__ void split_f32(const float* __restrict__ x,
                          __nv_bfloat16* __restrict__ hi,
                          __nv_bfloat16* __restrict__ lo, int n4)
{
    int i = blockIdx.x * blockDim.x + threadIdx.x;
    if (i >= n4) return;
    float4 v = ((const float4*)x)[i];
    __nv_bfloat16 h0 = __float2bfloat16(v.x);
    __nv_bfloat16 h1 = __float2bfloat16(v.y);
    __nv_bfloat16 h2 = __float2bfloat16(v.z);
    __nv_bfloat16 h3 = __float2bfloat16(v.w);
    __nv_bfloat16 l0 = __float2bfloat16(v.x - __bfloat162float(h0));
    __nv_bfloat16 l1 = __float2bfloat16(v.y - __bfloat162float(h1));
    __nv_bfloat16 l2 = __float2bfloat16(v.z - __bfloat162float(h2));
    __nv_bfloat16 l3 = __float2bfloat16(v.w - __bfloat162float(h3));
    ((__nv_bfloat162*)hi)[2 * i]     = __nv_bfloat162(h0, h1);
    ((__nv_bfloat162*)hi)[2 * i + 1] = __nv_bfloat162(h2, h3);
    ((__nv_bfloat162*)lo)[2 * i]     = __nv_bfloat162(l0, l1);
    ((__nv_bfloat162*)lo)[2 * i + 1] = __nv_bfloat162(l2, l3);
}

// transpose + split: W [KDIM][Nw] fp32 -> hiT/loT [Nw][KDIM] bf16.
// perm=1: rope-permute columns within each 128-wide head:
//   d -> 2*(d%64) + (d/64), so output fragment pairs (c, c+1) hold (x_d, x_{d+64}).
__global__ void splitT(const float* __restrict__ W,
                       __nv_bfloat16* __restrict__ hiT,
                       __nv_bfloat16* __restrict__ loT, int Nw, int perm)
{
    __shared__ float t[32][33];
    int n0 = blockIdx.x * 32, k0 = blockIdx.y * 32;
    int tx = threadIdx.x, ty = threadIdx.y;
#pragma unroll
    for (int i = 0; i < 32; i += 8)
        t[ty + i][tx] = W[(size_t)(k0 + ty + i) * Nw + n0 + tx];
    __syncthreads();
#pragma unroll
    for (int i = 0; i < 32; i += 8) {
        float v = t[tx][ty + i];
        __nv_bfloat16 h = __float2bfloat16(v);
        int n = n0 + ty + i;
        if (perm) {
            int d = n & 127;
            n = (n & ~127) | (((d & 63) << 1) | (d >> 6));
        }
        size_t o = (size_t)n * KDIM + k0 + tx;
        hiT[o] = h;
        loT[o] = __float2bfloat16(v - __bfloat162float(h));
    }
}

// ================= tensor-core GEMM via mma.sync, bf16x3 split =================
// Up to 3 fused problem sets along blockIdx.x (range-selected).
// mode 0: rope (table) + hi/lo bf16 split, register-only (B rope-permuted)
// mode 1: hi/lo bf16 split from registers (V projection)
// mode 2: plain fp32 epilogue (output projection)
#define BK 32
#define APITCH_B 80
#define TILE_B (128 * APITCH_B)
#define BUF_B (4 * TILE_B)
#define GSMEM (2 * BUF_B)
#define NCHG (KDIM / BK)

struct GemmProb {
    const __nv_bfloat16* Bhi;
    const __nv_bfloat16* Blo;
    void* o1;        // mode 0/1: bf16 hi; mode 2: fp32 C
    void* o2;        // mode 0/1: bf16 lo
    int N;
    int mode;
    float scale;
};

__global__ __launch_bounds__(256, 2)
void gemm_mma(const __nv_bfloat16* __restrict__ Ahi,
              const __nv_bfloat16* __restrict__ Alo,
              const float2* __restrict__ rope_tab,
              GemmProb p0, GemmProb p1, GemmProb p2, int c0, int c1)
{
    extern __shared__ char smem[];
    const uint32_t sb = smem_u32(smem);
    const int tid = threadIdx.x;
    const int wid = tid >> 5, lane = tid & 31;
    const int wm = wid >> 2, wn = wid & 3;
    const int m0 = blockIdx.y << 7;

    int bx = blockIdx.x;
    const GemmProb* p;
    if (bx < c0)       { p = &p0; }
    else if (bx < c1)  { p = &p1; bx -= c0; }
    else               { p = &p2; bx -= c1; }
    const int n0 = bx << 7;
    const __nv_bfloat16* Bhi = p->Bhi;
    const __nv_bfloat16* Blo = p->Blo;
    const int N = p->N;

    const char* gsrc[4];
    gsrc[0] = (const char*)(Ahi + (size_t)m0 * KDIM);
    gsrc[1] = (const char*)(Alo + (size_t)m0 * KDIM);
    gsrc[2] = (const char*)(Bhi + (size_t)n0 * KDIM);
    gsrc[3] = (const char*)(Blo + (size_t)n0 * KDIM);

    const int r0 = tid >> 2, s0 = tid & 3;
    const int r1 = (tid + 256) >> 2, s1 = tid & 3;

    auto load_chunk = [&](int c) {
        const int buf = c & 1;
#pragma unroll
        for (int t = 0; t < 4; t++) {
            const char* gb = gsrc[t] + (size_t)c * (BK * 2);
            uint32_t st = sb + buf * BUF_B + t * TILE_B;
            CP_ASYNC16(st + r0 * APITCH_B + s0 * 16,
                       gb + (size_t)r0 * (KDIM * 2) + s0 * 16);
            CP_ASYNC16(st + r1 * APITCH_B + s1 * 16,
                       gb + (size_t)r1 * (KDIM * 2) + s1 * 16);
        }
    };

    float acc[4][4][4];
#pragma unroll
    for (int i = 0; i < 4; i++)
#pragma unroll
        for (int j = 0; j < 4; j++)
#pragma unroll
            for (int e = 0; e < 4; e++) acc[i][j][e] = 0.0f;

    const uint32_t a_off = (uint32_t)((lane & 15) * APITCH_B + (lane >> 4) * 16);
    const int bg = lane >> 3;
    const uint32_t b_off = (uint32_t)(((bg >> 1) * 8 + (lane & 7)) * APITCH_B + (bg & 1) * 16);

    load_chunk(0);
    CP_COMMIT();

    for (int c = 0; c < NCHG; ++c) {
        if (c + 1 < NCHG) load_chunk(c + 1);
        CP_COMMIT();
        CP_WAIT1();
        __syncthreads();

        const uint32_t base = sb + (c & 1) * BUF_B;
        const uint32_t sAhi = base + 0 * TILE_B + (wm * 64) * APITCH_B;
        const uint32_t sAlo = base + 1 * TILE_B + (wm * 64) * APITCH_B;
        const uint32_t sBhi = base + 2 * TILE_B + (wn * 32) * APITCH_B;
        const uint32_t sBlo = base + 3 * TILE_B + (wn * 32) * APITCH_B;
#pragma unroll
        for (int ks = 0; ks < 2; ks++) {
            const uint32_t koff = ks * 32;
            uint32_t ahi[4][4], bh[4][2];
#pragma unroll
            for (int fm = 0; fm < 4; fm++)
                ldsm_x4(ahi[fm], sAhi + fm * 16 * APITCH_B + koff + a_off);
#pragma unroll
            for (int f2 = 0; f2 < 2; f2++) {
                uint32_t r[4];
                ldsm_x4(r, sBhi + f2 * 16 * APITCH_B + koff + b_off);
                bh[2 * f2][0] = r[0]; bh[2 * f2][1] = r[1];
                bh[2 * f2 + 1][0] = r[2]; bh[2 * f2 + 1][1] = r[3];
            }
            // ahi x bhi
#pragma unroll
            for (int fm = 0; fm < 4; fm++)
#pragma unroll
                for (int fn = 0; fn < 4; fn++)
                    mma16816(acc[fm][fn], ahi[fm], bh[fn]);
            {
                uint32_t bl[4][2];
#pragma unroll
                for (int f2 = 0; f2 < 2; f2++) {
                    uint32_t r[4];
                    ldsm_x4(r, sBlo + f2 * 16 * APITCH_B + koff + b_off);
                    bl[2 * f2][0] = r[0]; bl[2 * f2][1] = r[1];
                    bl[2 * f2 + 1][0] = r[2]; bl[2 * f2 + 1][1] = r[3];
                }
                // ahi x blo
#pragma unroll
                for (int fm = 0; fm < 4; fm++)
#pragma unroll
                    for (int fn = 0; fn < 4; fn++)
                        mma16816(acc[fm][fn], ahi[fm], bl[fn]);
            }
            // alo x bhi (ahi registers dead; reuse)
            uint32_t alo[4][4];
#pragma unroll
            for (int fm = 0; fm < 4; fm++)
                ldsm_x4(alo[fm], sAlo + fm * 16 * APITCH_B + koff + a_off);
#pragma unroll
            for (int fm = 0; fm < 4; fm++)
#pragma unroll
                for (int fn = 0; fn < 4; fn++)
                    mma16816(acc[fm][fn], alo[fm], bh[fn]);
        }
        __syncthreads();
    }

    const int erow = lane >> 2;
    const int ecol = (lane & 3) * 2;
    const int mode = p->mode;

    if (mode == 2) {
        float* C = (float*)p->o1;
#pragma unroll
        for (int fm = 0; fm < 4; fm++) {
#pragma unroll
            for (int fn = 0; fn < 4; fn++) {
                int row = m0 + wm * 64 + fm * 16 + erow;
                int col = n0 + wn * 32 + fn * 8 + ecol;
                *(float2*)(C + (size_t)row * N + col) =
                    make_float2(acc[fm][fn][0], acc[fm][fn][1]);
                *(float2*)(C + (size_t)(row + 8) * N + col) =
                    make_float2(acc[fm][fn][2], acc[fm][fn][3]);
            }
        }
    } else if (mode == 1) {
        __nv_bfloat16* hi = (__nv_bfloat16*)p->o1;
        __nv_bfloat16* lo = (__nv_bfloat16*)p->o2;
#pragma unroll
        for (int fm = 0; fm < 4; fm++) {
#pragma unroll
            for (int fn = 0; fn < 4; fn++) {
                int row = m0 + wm * 64 + fm * 16 + erow;
                int col = n0 + wn * 32 + fn * 8 + ecol;
#pragma unroll
                for (int half = 0; half < 2; half++) {
                    float v0 = acc[fm][fn][2 * half];
                    float v1 = acc[fm][fn][2 * half + 1];
                    uint32_t hh = packbf(v0, v1);
                    __nv_bfloat162* hp = (__nv_bfloat162*)&hh;
                    uint32_t ll = packbf(v0 - __bfloat162float(hp->x),
                                         v1 - __bfloat162float(hp->y));
                    size_t off = (size_t)(row + half * 8) * N + col;
                    *(uint32_t*)(hi + off) = hh;
                    *(uint32_t*)(lo + off) = ll;
                }
            }
        }
    } else {
        // mode 0: register-only RoPE (B rope-permuted: (c, c+1) = (x_d, x_{d+64}))
        __nv_bfloat16* hi = (__nv_bfloat16*)p->o1;
        __nv_bfloat16* lo = (__nv_bfloat16*)p->o2;
        const float scale = p->scale;
#pragma unroll
        for (int fm = 0; fm < 4; fm++) {
#pragma unroll
            for (int fn = 0; fn < 4; fn++) {
                int row = m0 + wm * 64 + fm * 16 + erow;
                int dd = (wn * 32 + fn * 8 + ecol) >> 1;   // 0..63
#pragma unroll
                for (int half = 0; half < 2; half++) {
                    int rowh = row + half * 8;
                    float v0 = acc[fm][fn][2 * half];
                    float v1 = acc[fm][fn][2 * half + 1];
                    float2 t = __ldg(rope_tab + (rowh & (SEQ - 1)) * 64 + dd);
                    float y0 = (v0 * t.x - v1 * t.y) * scale;
                    float y1 = (v1 * t.x + v0 * t.y) * scale;
                    __nv_bfloat16 h0 = __float2bfloat16(y0);
                    __nv_bfloat16 h1 = __float2bfloat16(y1);
                    size_t off = (size_t)rowh * N + n0 + dd;
                    hi[off]      = h0;
                    hi[off + 64] = h1;
                    lo[off]      = __float2bfloat16(y0 - __bfloat162float(h0));
                    lo[off + 64] = __float2bfloat16(y1 - __bfloat162float(h1));
                }
            }
        }
    }
}

// ================= tensor-core flash attention (causal, GQA) =================
#define FPB 272                         // smem row pitch bytes (136 bf16)
#define QTILE_B (128 * FPB)             // 34816
#define KVTILE_B (64 * FPB)             // 17408
#define SMB_QHI 0
#define SMB_QLO QTILE_B
#define SMB_KV  (2 * QTILE_B)           // 8 kv tiles follow (2 bufs x 4)
#define FLASH_SMEM_B (2 * QTILE_B + 8 * KVTILE_B)  // 208896

__global__ __launch_bounds__(256, 1)
void flash_mma(const __nv_bfloat16* __restrict__ Qhi,
               const __nv_bfloat16* __restrict__ Qlo,
               const __nv_bfloat16* __restrict__ Khi,
               const __nv_bfloat16* __restrict__ Klo,
               const __nv_bfloat16* __restrict__ Vhi,
               const __nv_bfloat16* __restrict__ Vlo,
               __nv_bfloat16* __restrict__ Ohi,
               __nv_bfloat16* __restrict__ Olo)
{
    extern __shared__ char smem[];
    const uint32_t sb = smem_u32(smem);
    const int tid = threadIdx.x;
    const int wid = tid >> 5, lane = tid & 31;
    const int qt = 15 - (int)blockIdx.x;     // heavy tiles first
    const int h = blockIdx.y, b = blockIdx.z;
    const int g = h >> 2;
    const int q0 = qt << 7;
    const int ntiles = 2 * qt + 2;           // 64-col kv tiles

    const uint32_t a_off = (uint32_t)((lane & 15) * FPB + (lane >> 4) * 16);

    const char* kh_base = (const char*)(Khi + (size_t)(b * SEQ) * KVW + g * HD);
    const char* kl_base = (const char*)(Klo + (size_t)(b * SEQ) * KVW + g * HD);
    const char* vh_base = (const char*)(Vhi + (size_t)(b * SEQ) * KVW + g * HD);
    const char* vl_base = (const char*)(Vlo + (size_t)(b * SEQ) * KVW + g * HD);

    auto issue_kv = [&](int j) {
        const uint32_t dst = sb + SMB_KV + (j & 1) * (4 * KVTILE_B);
        const int k0 = j << 6;
        const char* srcs[4] = {kh_base, kl_base, vh_base, vl_base};
#pragma unroll
        for (int t = 0; t < 4; t++) {
#pragma unroll
            for (int i = 0; i < 4; i++) {
                int idx = i * 256 + tid;         // 0..1023
                int row = idx >> 4, c = idx & 15;
                CP_ASYNC16(dst + t * KVTILE_B + row * FPB + c * 16,
                           srcs[t] + (size_t)(k0 + row) * (KVW * 2) + c * 16);
            }
        }
    };

    // ---- prologue: Q tiles + first two KV tiles ----
    {
        const char* qh = (const char*)(Qhi + (size_t)(b * SEQ + q0) * HIDDEN + h * HD);
        const char* ql = (const char*)(Qlo + (size_t)(b * SEQ + q0) * HIDDEN + h * HD);
#pragma unroll
        for (int i = 0; i < 8; i++) {
            int idx = i * 256 + tid;
            int row = idx >> 4, c = idx & 15;
            CP_ASYNC16(sb + SMB_QHI + row * FPB + c * 16,
                       qh + (size_t)row * (HIDDEN * 2) + c * 16);
            CP_ASYNC16(sb + SMB_QLO + row * FPB + c * 16,
                       ql + (size_t)row * (HIDDEN * 2) + c * 16);
        }
        CP_COMMIT();
    }
    issue_kv(0);
    CP_COMMIT();
    issue_kv(1);   // ntiles >= 2 always
    CP_COMMIT();

    float o[16][4];
#pragma unroll
    for (int nt = 0; nt < 16; nt++)
#pragma unroll
        for (int e = 0; e < 4; e++) o[nt][e] = 0.0f;
    float mrow0 = -INFINITY, mrow1 = -INFINITY, lrow0 = 0.0f, lrow1 = 0.0f;

    for (int j = 0; j < ntiles; j++) {
        if (j + 1 < ntiles) { CP_WAIT1(); } else { CP_WAIT0(); }
        __syncthreads();

        const uint32_t kvb = sb + SMB_KV + (j & 1) * (4 * KVTILE_B);
        const uint32_t skhi = kvb;
        const uint32_t sklo = kvb + KVTILE_B;
        const uint32_t svhi = kvb + 2 * KVTILE_B;
        const uint32_t svlo = kvb + 3 * KVTILE_B;
        const int k0 = j << 6;

        // ---- S = Q . K^T (3 passes hi/lo), 128 q-rows x 64 k-cols ----
        float s[8][4];
#pragma unroll
        for (int nt = 0; nt < 8; nt++)
#pragma unroll
            for (int e = 0; e < 4; e++) s[nt][e] = 0.0f;

#pragma unroll
        for (int ks = 0; ks < 8; ks++) {
            uint32_t ahi[4], alo[4];
            ldsm_x4(ahi, sb + SMB_QHI + (wid * 16) * FPB + ks * 32 + a_off);
            ldsm_x4(alo, sb + SMB_QLO + (wid * 16) * FPB + ks * 32 + a_off);
#pragma unroll
            for (int nt2 = 0; nt2 < 4; nt2++) {
                uint32_t kh[4], kl[4];
                ldsm_x4(kh, skhi + (nt2 * 16) * FPB + ks * 32 + a_off);
                ldsm_x4(kl, sklo + (nt2 * 16) * FPB + ks * 32 + a_off);
                uint32_t bh0[2] = {kh[0], kh[2]}, bh1[2] = {kh[1], kh[3]};
                uint32_t bl0[2] = {kl[0], kl[2]}, bl1[2] = {kl[1], kl[3]};
                mma16816(s[2 * nt2],     ahi, bh0);
                mma16816(s[2 * nt2 + 1], ahi, bh1);
                mma16816(s[2 * nt2],     ahi, bl0);
                mma16816(s[2 * nt2 + 1], ahi, bl1);
                mma16816(s[2 * nt2],     alo, bh0);
                mma16816(s[2 * nt2 + 1], alo, bh1);
            }
        }

        // ---- causal mask (diagonal block tiles) ----
        if (k0 + 64 > q0) {
            const int rq = q0 + wid * 16 + (lane >> 2) - k0;
            const int lc = 2 * (lane & 3);
#pragma unroll
            for (int nt = 0; nt < 8; nt++) {
                int ln = nt * 8 + lc;
                if (ln > rq)         s[nt][0] = -1e30f;
                if (ln + 1 > rq)     s[nt][1] = -1e30f;
                if (ln > rq + 8)     s[nt][2] = -1e30f;
                if (ln + 1 > rq + 8) s[nt][3] = -1e30f;
            }
        }

        // ---- online softmax (log2-domain; Q pre-scaled by log2e/sqrt(d)) ----
        float mx0 = -1e30f, mx1 = -1e30f;
#pragma unroll
        for (int nt = 0; nt < 8; nt++) {
            mx0 = fmaxf(mx0, fmaxf(s[nt][0], s[nt][1]));
            mx1 = fmaxf(mx1, fmaxf(s[nt][2], s[nt][3]));
        }
        mx0 = fmaxf(mx0, __shfl_xor_sync(0xffffffffu, mx0, 1));
        mx0 = fmaxf(mx0, __shfl_xor_sync(0xffffffffu, mx0, 2));
        mx1 = fmaxf(mx1, __shfl_xor_sync(0xffffffffu, mx1, 1));
        mx1 = fmaxf(mx1, __shfl_xor_sync(0xffffffffu, mx1, 2));
        const float newm0 = fmaxf(mrow0, mx0);
        const float newm1 = fmaxf(mrow1, mx1);

        float rs0 = 0.0f, rs1 = 0.0f;
#pragma unroll
        for (int nt = 0; nt < 8; nt++) {
            s[nt][0] = fexp2(s[nt][0] - newm0);
            s[nt][1] = fexp2(s[nt][1] - newm0);
            s[nt][2] = fexp2(s[nt][2] - newm1);
            s[nt][3] = fexp2(s[nt][3] - newm1);
            rs0 += s[nt][0] + s[nt][1];
            rs1 += s[nt][2] + s[nt][3];
        }
        rs0 += __shfl_xor_sync(0xffffffffu, rs0, 1);
        rs0 += __shfl_xor_sync(0xffffffffu, rs0, 2);
        rs1 += __shfl_xor_sync(0xffffffffu, rs1, 1);
        rs1 += __shfl_xor_sync(0xffffffffu, rs1, 2);

        const float al0 = fexp2(mrow0 - newm0);
        const float al1 = fexp2(mrow1 - newm1);
        lrow0 = lrow0 * al0 + rs0;
        lrow1 = lrow1 * al1 + rs1;
        mrow0 = newm0;
        mrow1 = newm1;
#pragma unroll
        for (int nt = 0; nt < 16; nt++) {
            o[nt][0] *= al0; o[nt][1] *= al0;
            o[nt][2] *= al1; o[nt][3] *= al1;
        }

        // ---- O += P . V  (P hi/lo in registers, V hi/lo in smem; 3 passes) ----
#pragma unroll
        for (int t = 0; t < 4; t++) {
            float p00 = s[2 * t][0], p01 = s[2 * t][1];
            float p02 = s[2 * t][2], p03 = s[2 * t][3];
            float p10 = s[2 * t + 1][0], p11 = s[2 * t + 1][1];
            float p12 = s[2 * t + 1][2], p13 = s[2 * t + 1][3];
            uint32_t aph[4], apl[4];
            aph[0] = packbf(p00, p01);
            aph[1] = packbf(p02, p03);
            aph[2] = packbf(p10, p11);
            aph[3] = packbf(p12, p13);
            {
                __nv_bfloat162* hp;
                hp = (__nv_bfloat162*)&aph[0];
                apl[0] = packbf(p00 - __bfloat162float(hp->x), p01 - __bfloat162float(hp->y));
                hp = (__nv_bfloat162*)&aph[1];
                apl[1] = packbf(p02 - __bfloat162float(hp->x), p03 - __bfloat162float(hp->y));
                hp = (__nv_bfloat162*)&aph[2];
                apl[2] = packbf(p10 - __bfloat162float(hp->x), p11 - __bfloat162float(hp->y));
                hp = (__nv_bfloat162*)&aph[3];
                apl[3] = packbf(p12 - __bfloat162float(hp->x), p13 - __bfloat162float(hp->y));
            }
#pragma unroll
            for (int nt2 = 0; nt2 < 8; nt2++) {
                uint32_t vh[4], vl[4];
                ldsm_x4_t(vh, svhi + (t * 16) * FPB + nt2 * 32 + a_off);
                ldsm_x4_t(vl, svlo + (t * 16) * FPB + nt2 * 32 + a_off);
                uint32_t bh0[2] = {vh[0], vh[1]}, bh1[2] = {vh[2], vh[3]};
                uint32_t bl0[2] = {vl[0], vl[1]}, bl1[2] = {vl[2], vl[3]};
                mma16816(o[2 * nt2],     aph, bh0);
                mma16816(o[2 * nt2 + 1], aph, bh1);
                mma16816(o[2 * nt2],     aph, bl0);
                mma16816(o[2 * nt2 + 1], aph, bl1);
                mma16816(o[2 * nt2],     apl, bh0);
                mma16816(o[2 * nt2 + 1], apl, bh1);
            }
        }

        __syncthreads();               // done reading buffer (j & 1)
        if (j + 2 < ntiles) {
            issue_kv(j + 2);
            CP_COMMIT();
        }
    }

    // ---- epilogue: normalize, split to hi/lo bf16, write ----
    const float invl0 = 1.0f / lrow0;
    const float invl1 = 1.0f / lrow1;
    const int grow = b * SEQ + q0 + wid * 16 + (lane >> 2);
    const size_t cbase = (size_t)grow * HIDDEN + h * HD + 2 * (lane & 3);
#pragma unroll
    for (int nt = 0; nt < 16; nt++) {
        float v0 = o[nt][0] * invl0, v1 = o[nt][1] * invl0;
        float v2 = o[nt][2] * invl1, v3 = o[nt][3] * invl1;
        uint32_t h01 = packbf(v0, v1);
        uint32_t h23 = packbf(v2, v3);
        __nv_bfloat162* hp01 = (__nv_bfloat162*)&h01;
        __nv_bfloat162* hp23 = (__nv_bfloat162*)&h23;
        uint32_t l01 = packbf(v0 - __bfloat162float(hp01->x),
                              v1 - __bfloat162float(hp01->y));
        uint32_t l23 = packbf(v2 - __bfloat162float(hp23->x),
                              v3 - __bfloat162float(hp23->y));
        *(uint32_t*)(Ohi + cbase + nt * 8) = h01;
        *(uint32_t*)(Olo + cbase + nt * 8) = l01;
        *(uint32_t*)(Ohi + cbase + (size_t)8 * HIDDEN + nt * 8) = h23;
        *(uint32_t*)(Olo + cbase + (size_t)8 * HIDDEN + nt * 8) = l23;
    }
}

// ---------------- launch ----------------
extern "C" void kernel_launch(void* const* d_in, const int* in_sizes, int n_in,
                              void* d_out, int out_size)
{
    const float* x  = (const float*)d_in[0];
    const float* wq = (const float*)d_in[1];
    const float* wk = (const float*)d_in[2];
    const float* wv = (const float*)d_in[3];
    const float* wo = (const float*)d_in[4];
    float* out = (float*)d_out;

    float2* ropep;
    __nv_bfloat16 *xhi, *xlo, *qhi, *qlo, *ahi, *alo, *khi, *klo, *vhi, *vlo;
    __nv_bfloat16 *wqhi, *wqlo, *wkhi, *wklo, *wvhi, *wvlo, *wohi, *wolo;
    cudaGetSymbolAddress((void**)&ropep, g_rope);
    cudaGetSymbolAddress((void**)&xhi, g_xhi);
    cudaGetSymbolAddress((void**)&xlo, g_xlo);
    cudaGetSymbolAddress((void**)&qhi, g_qhi);
    cudaGetSymbolAddress((void**)&qlo, g_qlo);
    cudaGetSymbolAddress((void**)&ahi, g_ahi);
    cudaGetSymbolAddress((void**)&alo, g_alo);
    cudaGetSymbolAddress((void**)&khi, g_khi);
    cudaGetSymbolAddress((void**)&klo, g_klo);
    cudaGetSymbolAddress((void**)&vhi, g_vhi);
    cudaGetSymbolAddress((void**)&vlo, g_vlo);
    cudaGetSymbolAddress((void**)&wqhi, g_wqhi);
    cudaGetSymbolAddress((void**)&wqlo, g_wqlo);
    cudaGetSymbolAddress((void**)&wkhi, g_wkhi);
    cudaGetSymbolAddress((void**)&wklo, g_wklo);
    cudaGetSymbolAddress((void**)&wvhi, g_wvhi);
    cudaGetSymbolAddress((void**)&wvlo, g_wvlo);
    cudaGetSymbolAddress((void**)&wohi, g_wohi);
    cudaGetSymbolAddress((void**)&wolo, g_wolo);

    cudaFuncSetAttribute(gemm_mma,
                         cudaFuncAttributeMaxDynamicSharedMemorySize, GSMEM);
    cudaFuncSetAttribute(flash_mma,
                         cudaFuncAttributeMaxDynamicSharedMemorySize, FLASH_SMEM_B);

    const int n4x = MROWS * KDIM / 4;

    GemmProb pq = {wqhi, wqlo, qhi, qlo, HIDDEN, 0, QSCALE_L2E};
    GemmProb pk = {wkhi, wklo, khi, klo, KVW, 0, 1.0f};
    GemmProb pv = {wvhi, wvlo, vhi, vlo, KVW, 1, 1.0f};
    GemmProb po = {wohi, wolo, out, nullptr, HIDDEN, 2, 1.0f};

    // rope table + input split + weight splits (wq/wk rope-permuted)
    rope_table<<<SEQ * 64 / 256, 256>>>(ropep);
    split_f32<<<(n4x + 255) / 256, 256>>>(x, xhi, xlo, n4x);
    splitT<<<dim3(HIDDEN / 32, KDIM / 32), dim3(32, 8)>>>(wq, wqhi, wqlo, HIDDEN, 1);
    splitT<<<dim3(KVW / 32, KDIM / 32), dim3(32, 8)>>>(wk, wkhi, wklo, KVW, 1);
    splitT<<<dim3(KVW / 32, KDIM / 32), dim3(32, 8)>>>(wv, wvhi, wvlo, KVW, 0);

    // fused Q+K+V projection with register-only RoPE/split epilogues
    gemm_mma<<<dim3(24, MROWS / 128), 256, GSMEM>>>(xhi, xlo, ropep, pq, pk, pv, 16, 20);

    // causal flash attention (writes att hi/lo directly)
    flash_mma<<<dim3(SEQ / 128, NHEADS, BATCH), 256, FLASH_SMEM_B>>>(
        qhi, qlo, khi, klo, vhi, vlo, ahi, alo);

    // wo split (deferred) + output projection
    splitT<<<dim3(HIDDEN / 32, KDIM / 32), dim3(32, 8)>>>(wo, wohi, wolo, HIDDEN, 0);
    gemm_mma<<<dim3(16, MROWS / 128), 256, GSMEM>>>(ahi, alo, ropep, po, po, po, 16, 16);
}

// round 16
// speedup vs baseline: 1.0317x; 1.0317x over previous
#include <cuda_runtime.h>
#include <cuda_bf16.h>
#include <stdint.h>
#include <math.h>

#define HIDDEN 2048
#define NHEADS 16
#define NKV 4
#define HD 128
#define SEQ 2048
#define BATCH 2
#define MROWS (BATCH * SEQ)   // 4096
#define KVW (NKV * HD)        // 512
#define KDIM 2048
// 1/sqrt(128) * log2(e)  (exp2-based softmax)
#define QSCALE_L2E 0.1275174500772518f

// ---------------- scratch (no allocations allowed) ----------------
__device__ __align__(128) float2 g_rope[SEQ * 64];
__device__ __align__(128) float g_q[MROWS * HIDDEN];
__device__ __align__(128) float g_k[MROWS * KVW];
__device__ __align__(128) float g_v[MROWS * KVW];
__device__ __align__(128) __nv_bfloat16 g_xhi[MROWS * KDIM];
__device__ __align__(128) __nv_bfloat16 g_xlo[MROWS * KDIM];
__device__ __align__(128) __nv_bfloat16 g_ahi[MROWS * KDIM];
__device__ __align__(128) __nv_bfloat16 g_alo[MROWS * KDIM];
__device__ __align__(128) __nv_bfloat16 g_khi[MROWS * KVW];
__device__ __align__(128) __nv_bfloat16 g_klo[MROWS * KVW];
__device__ __align__(128) __nv_bfloat16 g_vhi[MROWS * KVW];
__device__ __align__(128) __nv_bfloat16 g_vlo[MROWS * KVW];
__device__ __align__(128) __nv_bfloat16 g_wqhi[HIDDEN * KDIM];  // transposed [N][K]
__device__ __align__(128) __nv_bfloat16 g_wqlo[HIDDEN * KDIM];
__device__ __align__(128) __nv_bfloat16 g_wkhi[KVW * KDIM];
__device__ __align__(128) __nv_bfloat16 g_wklo[KVW * KDIM];
__device__ __align__(128) __nv_bfloat16 g_wvhi[KVW * KDIM];
__device__ __align__(128) __nv_bfloat16 g_wvlo[KVW * KDIM];
__device__ __align__(128) __nv_bfloat16 g_wohi[HIDDEN * KDIM];
__device__ __align__(128) __nv_bfloat16 g_wolo[HIDDEN * KDIM];

// ================= helpers =================
__device__ __forceinline__ uint32_t smem_u32(const void* p) {
    uint32_t a;
    asm("{ .reg .u64 t; cvta.to.shared.u64 t, %1; cvt.u32.u64 %0, t; }"
        : "=r"(a) : "l"(p));
    return a;
}
#define CP_ASYNC16(dst, src) \
    asm volatile("cp.async.cg.shared.global [%0], [%1], 16;" :: "r"(dst), "l"(src) : "memory")
#define CP_COMMIT() asm volatile("cp.async.commit_group;" ::: "memory")
#define CP_WAIT2()  asm volatile("cp.async.wait_group 2;" ::: "memory")
#define CP_WAIT1()  asm volatile("cp.async.wait_group 1;" ::: "memory")
#define CP_WAIT0()  asm volatile("cp.async.wait_group 0;" ::: "memory")

__device__ __forceinline__ void ldsm_x4(uint32_t* r, uint32_t addr) {
    asm volatile("ldmatrix.sync.aligned.m8n8.x4.shared.b16 {%0,%1,%2,%3}, [%4];"
                 : "=r"(r[0]), "=r"(r[1]), "=r"(r[2]), "=r"(r[3]) : "r"(addr));
}
__device__ __forceinline__ void ldsm_x4_t(uint32_t* r, uint32_t addr) {
    asm volatile("ldmatrix.sync.aligned.m8n8.x4.trans.shared.b16 {%0,%1,%2,%3}, [%4];"
                 : "=r"(r[0]), "=r"(r[1]), "=r"(r[2]), "=r"(r[3]) : "r"(addr));
}
__device__ __forceinline__ void mma16816(float* d, const uint32_t* a, const uint32_t* b) {
    asm volatile("mma.sync.aligned.m16n8k16.row.col.f32.bf16.bf16.f32 "
                 "{%0,%1,%2,%3}, {%4,%5,%6,%7}, {%8,%9}, {%0,%1,%2,%3};"
                 : "+f"(d[0]), "+f"(d[1]), "+f"(d[2]), "+f"(d[3])
                 : "r"(a[0]), "r"(a[1]), "r"(a[2]), "r"(a[3]), "r"(b[0]), "r"(b[1]));
}
__device__ __forceinline__ uint32_t packbf(float x, float y) {
    __nv_bfloat162 t;
    t.x = __float2bfloat16_rn(x);
    t.y = __float2bfloat16_rn(y);
    return *(uint32_t*)&t;
}
__device__ __forceinline__ float fexp2(float x) {
    float y;
    asm("ex2.approx.f32 %0, %1;" : "=f"(y) : "f"(x));
    return y;
}

// ================= RoPE cos/sin table =================
__global__ void rope_table(float2* __restrict__ tab)
{
    int idx = blockIdx.x * blockDim.x + threadIdx.x;   // SEQ*64
    int s = idx >> 6;
    int d = idx & 63;
    float inv = exp2f(-(float)d * (13.287712379549449f / 64.0f));
    float ang = (float)s * inv;
    float sn, cs;
    sincosf(ang, &sn, &cs);
    tab[idx] = make_float2(cs, sn);
}

// ================= fp32 -> bf16 hi/lo split =================
__global__ void split_f32(const float* __restrict__ x,
                          __nv_bfloat16* __restrict__ hi,
                          __nv_bfloat16* __restrict__ lo, int n4)
{
    int i = blockIdx.x * blockDim.x + threadIdx.x;
    if (i >= n4) return;
    float4 v = ((const float4*)x)[i];
    __nv_bfloat16 h0 = __float2bfloat16(v.x);
    __nv_bfloat16 h1 = __float2bfloat16(v.y);
    __nv_bfloat16 h2 = __float2bfloat16(v.z);
    __nv_bfloat16 h3 = __float2bfloat16(v.w);
    __nv_bfloat16 l0 = __float2bfloat16(v.x - __bfloat162float(h0));
    __nv_bfloat16 l1 = __float2bfloat16(v.y - __bfloat162float(h1));
    __nv_bfloat16 l2 = __float2bfloat16(v.z - __bfloat162float(h2));
    __nv_bfloat16 l3 = __float2bfloat16(v.w - __bfloat162float(h3));
    ((__nv_bfloat162*)hi)[2 * i]     = __nv_bfloat162(h0, h1);
    ((__nv_bfloat162*)hi)[2 * i + 1] = __nv_bfloat162(h2, h3);
    ((__nv_bfloat162*)lo)[2 * i]     = __nv_bfloat162(l0, l1);
    ((__nv_bfloat162*)lo)[2 * i + 1] = __nv_bfloat162(l2, l3);
}

// transpose + split: W [KDIM][Nw] fp32 -> hiT/loT [Nw][KDIM] bf16
__global__ void splitT(const float* __restrict__ W,
                       __nv_bfloat16* __restrict__ hiT,
                       __nv_bfloat16* __restrict__ loT, int Nw)
{
    __shared__ float t[32][33];
    int n0 = blockIdx.x * 32, k0 = blockIdx.y * 32;
    int tx = threadIdx.x, ty = threadIdx.y;
#pragma unroll
    for (int i = 0; i < 32; i += 8)
        t[ty + i][tx] = W[(size_t)(k0 + ty + i) * Nw + n0 + tx];
    __syncthreads();
#pragma unroll
    for (int i = 0; i < 32; i += 8) {
        float v = t[tx][ty + i];
        __nv_bfloat16 h = __float2bfloat16(v);
        size_t o = (size_t)(n0 + ty + i) * KDIM + k0 + tx;
        hiT[o] = h;
        loT[o] = __float2bfloat16(v - __bfloat162float(h));
    }
}

// ---------------- fused glue: rope-q + rope-k + v-split (table-based) ---------
#define RQ_BLOCKS (MROWS * NHEADS * 64 / 256)       // 16384
#define RK_BLOCKS (MROWS * NKV * 64 / 256)          // 4096
#define VS_BLOCKS (MROWS * KVW / 4 / 256)           // 2048

__device__ __forceinline__ void rope_one(const float* __restrict__ x,
                                         const float2* __restrict__ tab,
                                         __nv_bfloat16* __restrict__ hi,
                                         __nv_bfloat16* __restrict__ lo,
                                         int idx, int heads, float scale)
{
    int d = idx & 63;
    int t = idx >> 6;
    int h = t % heads;
    int m = t / heads;
    int s = m & (SEQ - 1);

    float2 csn = __ldg(tab + s * 64 + d);

    size_t base = (size_t)m * (heads * 128) + h * 128 + d;
    float xlo = x[base];
    float xhi = x[base + 64];
    float y0 = (xlo * csn.x - xhi * csn.y) * scale;
    float y1 = (xhi * csn.x + xlo * csn.y) * scale;

    __nv_bfloat16 h0 = __float2bfloat16(y0);
    __nv_bfloat16 h1 = __float2bfloat16(y1);
    hi[base]      = h0;
    hi[base + 64] = h1;
    lo[base]      = __float2bfloat16(y0 - __bfloat162float(h0));
    lo[base + 64] = __float2bfloat16(y1 - __bfloat162float(h1));
}

__global__ void glue_kernel(const float* __restrict__ q,
                            const float* __restrict__ k,
                            const float* __restrict__ v,
                            const float2* __restrict__ tab,
                            __nv_bfloat16* __restrict__ qhi, __nv_bfloat16* __restrict__ qlo,
                            __nv_bfloat16* __restrict__ khi, __nv_bfloat16* __restrict__ klo,
                            __nv_bfloat16* __restrict__ vhi, __nv_bfloat16* __restrict__ vlo)
{
    int bx = blockIdx.x;
    if (bx < RQ_BLOCKS) {
        rope_one(q, tab, qhi, qlo, bx * 256 + threadIdx.x, NHEADS, QSCALE_L2E);
    } else if (bx < RQ_BLOCKS + RK_BLOCKS) {
        rope_one(k, tab, khi, klo, (bx - RQ_BLOCKS) * 256 + threadIdx.x, NKV, 1.0f);
    } else {
        int i = (bx - RQ_BLOCKS - RK_BLOCKS) * 256 + threadIdx.x;
        float4 vv = ((const float4*)v)[i];
        __nv_bfloat16 h0 = __float2bfloat16(vv.x);
        __nv_bfloat16 h1 = __float2bfloat16(vv.y);
        __nv_bfloat16 h2 = __float2bfloat16(vv.z);
        __nv_bfloat16 h3 = __float2bfloat16(vv.w);
        ((__nv_bfloat162*)vhi)[2 * i]     = __nv_bfloat162(h0, h1);
        ((__nv_bfloat162*)vhi)[2 * i + 1] = __nv_bfloat162(h2, h3);
        ((__nv_bfloat162*)vlo)[2 * i]     = __nv_bfloat162(
            __float2bfloat16(vv.x - __bfloat162float(h0)),
            __float2bfloat16(vv.y - __bfloat162float(h1)));
        ((__nv_bfloat162*)vlo)[2 * i + 1] = __nv_bfloat162(
            __float2bfloat16(vv.z - __bfloat162float(h2)),
            __float2bfloat16(vv.w - __bfloat162float(h3)));
    }
}

// ================= tensor-core GEMM via mma.sync, bf16x3 split =================
// Up to 3 fused (B, C) problem sets along blockIdx.x (range-selected).
#define BK 32
#define APITCH_B 80
#define TILE_B (128 * APITCH_B)
#define BUF_B (4 * TILE_B)
#define GSMEM (2 * BUF_B)
#define NCHG (KDIM / BK)

struct GemmProb {
    const __nv_bfloat16* Bhi;
    const __nv_bfloat16* Blo;
    float* C;
    int N;
};

__global__ __launch_bounds__(256, 2)
void gemm_mma(const __nv_bfloat16* __restrict__ Ahi,
              const __nv_bfloat16* __restrict__ Alo,
              GemmProb p0, GemmProb p1, GemmProb p2, int c0, int c1)
{
    extern __shared__ char smem[];
    const uint32_t sb = smem_u32(smem);
    const int tid = threadIdx.x;
    const int wid = tid >> 5, lane = tid & 31;
    const int wm = wid >> 2, wn = wid & 3;
    const int m0 = blockIdx.y << 7;

    int bx = blockIdx.x;
    const GemmProb* p;
    if (bx < c0)       { p = &p0; }
    else if (bx < c1)  { p = &p1; bx -= c0; }
    else               { p = &p2; bx -= c1; }
    const int n0 = bx << 7;
    const __nv_bfloat16* Bhi = p->Bhi;
    const __nv_bfloat16* Blo = p->Blo;
    float* C = p->C;
    const int N = p->N;

    const char* gsrc[4];
    gsrc[0] = (const char*)(Ahi + (size_t)m0 * KDIM);
    gsrc[1] = (const char*)(Alo + (size_t)m0 * KDIM);
    gsrc[2] = (const char*)(Bhi + (size_t)n0 * KDIM);
    gsrc[3] = (const char*)(Blo + (size_t)n0 * KDIM);

    const int r0 = tid >> 2, s0 = tid & 3;
    const int r1 = (tid + 256) >> 2, s1 = tid & 3;

    auto load_chunk = [&](int c) {
        const int buf = c & 1;
#pragma unroll
        for (int t = 0; t < 4; t++) {
            const char* gb = gsrc[t] + (size_t)c * (BK * 2);
            uint32_t st = sb + buf * BUF_B + t * TILE_B;
            CP_ASYNC16(st + r0 * APITCH_B + s0 * 16,
                       gb + (size_t)r0 * (KDIM * 2) + s0 * 16);
            CP_ASYNC16(st + r1 * APITCH_B + s1 * 16,
                       gb + (size_t)r1 * (KDIM * 2) + s1 * 16);
        }
    };

    float acc[4][4][4];
#pragma unroll
    for (int i = 0; i < 4; i++)
#pragma unroll
        for (int j = 0; j < 4; j++)
#pragma unroll
            for (int e = 0; e < 4; e++) acc[i][j][e] = 0.0f;

    const uint32_t a_off = (uint32_t)((lane & 15) * APITCH_B + (lane >> 4) * 16);
    const int bg = lane >> 3;
    const uint32_t b_off = (uint32_t)(((bg >> 1) * 8 + (lane & 7)) * APITCH_B + (bg & 1) * 16);

    load_chunk(0);
    CP_COMMIT();

    for (int c = 0; c < NCHG; ++c) {
        if (c + 1 < NCHG) load_chunk(c + 1);
        CP_COMMIT();
        CP_WAIT1();
        __syncthreads();

        const uint32_t base = sb + (c & 1) * BUF_B;
        const uint32_t sAhi = base + 0 * TILE_B + (wm * 64) * APITCH_B;
        const uint32_t sAlo = base + 1 * TILE_B + (wm * 64) * APITCH_B;
        const uint32_t sBhi = base + 2 * TILE_B + (wn * 32) * APITCH_B;
        const uint32_t sBlo = base + 3 * TILE_B + (wn * 32) * APITCH_B;
#pragma unroll
        for (int ks = 0; ks < 2; ks++) {
            const uint32_t koff = ks * 32;
            uint32_t ahi[4][4], bh[4][2];
#pragma unroll
            for (int fm = 0; fm < 4; fm++)
                ldsm_x4(ahi[fm], sAhi + fm * 16 * APITCH_B + koff + a_off);
#pragma unroll
            for (int f2 = 0; f2 < 2; f2++) {
                uint32_t r[4];
                ldsm_x4(r, sBhi + f2 * 16 * APITCH_B + koff + b_off);
                bh[2 * f2][0] = r[0]; bh[2 * f2][1] = r[1];
                bh[2 * f2 + 1][0] = r[2]; bh[2 * f2 + 1][1] = r[3];
            }
            // ahi x bhi
#pragma unroll
            for (int fm = 0; fm < 4; fm++)
#pragma unroll
                for (int fn = 0; fn < 4; fn++)
                    mma16816(acc[fm][fn], ahi[fm], bh[fn]);
            {
                uint32_t bl[4][2];
#pragma unroll
                for (int f2 = 0; f2 < 2; f2++) {
                    uint32_t r[4];
                    ldsm_x4(r, sBlo + f2 * 16 * APITCH_B + koff + b_off);
                    bl[2 * f2][0] = r[0]; bl[2 * f2][1] = r[1];
                    bl[2 * f2 + 1][0] = r[2]; bl[2 * f2 + 1][1] = r[3];
                }
                // ahi x blo
#pragma unroll
                for (int fm = 0; fm < 4; fm++)
#pragma unroll
                    for (int fn = 0; fn < 4; fn++)
                        mma16816(acc[fm][fn], ahi[fm], bl[fn]);
            }
            // alo x bhi (ahi registers dead; reuse)
            uint32_t alo[4][4];
#pragma unroll
            for (int fm = 0; fm < 4; fm++)
                ldsm_x4(alo[fm], sAlo + fm * 16 * APITCH_B + koff + a_off);
#pragma unroll
            for (int fm = 0; fm < 4; fm++)
#pragma unroll
                for (int fn = 0; fn < 4; fn++)
                    mma16816(acc[fm][fn], alo[fm], bh[fn]);
        }
        __syncthreads();
    }

    const int erow = lane >> 2;
    const int ecol = (lane & 3) * 2;
#pragma unroll
    for (int fm = 0; fm < 4; fm++) {
#pragma unroll
        for (int fn = 0; fn < 4; fn++) {
            int row = m0 + wm * 64 + fm * 16 + erow;
            int col = n0 + wn * 32 + fn * 8 + ecol;
            *(float2*)(C + (size_t)row * N + col) =
                make_float2(acc[fm][fn][0], acc[fm][fn][1]);
            *(float2*)(C + (size_t)(row + 8) * N + col) =
                make_float2(acc[fm][fn][2], acc[fm][fn][3]);
        }
    }
}

// ================= tensor-core flash attention (causal, GQA) =================
// Occupancy-2 variant: 128 threads (4 warps), q-tile 64 rows, KV step 32 cols,
// double-buffered; Q fragments hoisted into registers.
#define FPB 272                          // smem row pitch bytes (136 bf16)
#define F_QTILE_B (64 * FPB)             // 17408
#define F_KVTILE_B (32 * FPB)            // 8704
#define SMB_QHI 0
#define SMB_QLO F_QTILE_B
#define SMB_KV  (2 * F_QTILE_B)          // 34816; 2 bufs x 4 tiles follow
#define FLASH_SMEM_B (2 * F_QTILE_B + 8 * F_KVTILE_B)  // 104448 -> 2 CTAs/SM

__global__ __launch_bounds__(128, 2)
void flash_mma(const __nv_bfloat16* __restrict__ Qhi,
               const __nv_bfloat16* __restrict__ Qlo,
               const __nv_bfloat16* __restrict__ Khi,
               const __nv_bfloat16* __restrict__ Klo,
               const __nv_bfloat16* __restrict__ Vhi,
               const __nv_bfloat16* __restrict__ Vlo,
               __nv_bfloat16* __restrict__ Ohi,
               __nv_bfloat16* __restrict__ Olo)
{
    extern __shared__ char smem[];
    const uint32_t sb = smem_u32(smem);
    const int tid = threadIdx.x;
    const int wid = tid >> 5, lane = tid & 31;
    const int qt = 31 - (int)blockIdx.x;     // heavy tiles first
    const int h = blockIdx.y, b = blockIdx.z;
    const int g = h >> 2;
    const int q0 = qt << 6;                  // 64-row q tile
    const int ntiles = 2 * qt + 2;           // 32-col kv tiles

    const uint32_t a_off = (uint32_t)((lane & 15) * FPB + (lane >> 4) * 16);

    const char* kh_base = (const char*)(Khi + (size_t)(b * SEQ) * KVW + g * HD);
    const char* kl_base = (const char*)(Klo + (size_t)(b * SEQ) * KVW + g * HD);
    const char* vh_base = (const char*)(Vhi + (size_t)(b * SEQ) * KVW + g * HD);
    const char* vl_base = (const char*)(Vlo + (size_t)(b * SEQ) * KVW + g * HD);

    auto issue_kv = [&](int j) {
        const uint32_t dst = sb + SMB_KV + (j & 1) * (4 * F_KVTILE_B);
        const int k0 = j << 5;
        const char* srcs[4] = {kh_base, kl_base, vh_base, vl_base};
#pragma unroll
        for (int t = 0; t < 4; t++) {
#pragma unroll
            for (int i = 0; i < 4; i++) {
                int idx = i * 128 + tid;         // 0..511
                int row = idx >> 4, c = idx & 15;
                CP_ASYNC16(dst + t * F_KVTILE_B + row * FPB + c * 16,
                           srcs[t] + (size_t)(k0 + row) * (KVW * 2) + c * 16);
            }
        }
    };

    // ---- prologue: Q tiles + first two KV tiles ----
    {
        const char* qh = (const char*)(Qhi + (size_t)(b * SEQ + q0) * HIDDEN + h * HD);
        const char* ql = (const char*)(Qlo + (size_t)(b * SEQ + q0) * HIDDEN + h * HD);
#pragma unroll
        for (int i = 0; i < 8; i++) {
            int idx = i * 128 + tid;             // 0..1023
            int row = idx >> 4, c = idx & 15;
            CP_ASYNC16(sb + SMB_QHI + row * FPB + c * 16,
                       qh + (size_t)row * (HIDDEN * 2) + c * 16);
            CP_ASYNC16(sb + SMB_QLO + row * FPB + c * 16,
                       ql + (size_t)row * (HIDDEN * 2) + c * 16);
        }
        CP_COMMIT();
    }
    issue_kv(0);
    CP_COMMIT();
    issue_kv(1);   // ntiles >= 2 always
    CP_COMMIT();

    // ---- hoist Q fragments into registers (loop-invariant) ----
    CP_WAIT2();
    __syncthreads();
    uint32_t qfh[8][4], qfl[8][4];
#pragma unroll
    for (int ks = 0; ks < 8; ks++) {
        ldsm_x4(qfh[ks], sb + SMB_QHI + (wid * 16) * FPB + ks * 32 + a_off);
        ldsm_x4(qfl[ks], sb + SMB_QLO + (wid * 16) * FPB + ks * 32 + a_off);
    }

    float o[16][4];
#pragma unroll
    for (int nt = 0; nt < 16; nt++)
#pragma unroll
        for (int e = 0; e < 4; e++) o[nt][e] = 0.0f;
    float mrow0 = -INFINITY, mrow1 = -INFINITY, lrow0 = 0.0f, lrow1 = 0.0f;

    for (int j = 0; j < ntiles; j++) {
        if (j + 1 < ntiles) { CP_WAIT1(); } else { CP_WAIT0(); }
        __syncthreads();

        const uint32_t kvb = sb + SMB_KV + (j & 1) * (4 * F_KVTILE_B);
        const uint32_t skhi = kvb;
        const uint32_t sklo = kvb + F_KVTILE_B;
        const uint32_t svhi = kvb + 2 * F_KVTILE_B;
        const uint32_t svlo = kvb + 3 * F_KVTILE_B;
        const int k0 = j << 5;

        // ---- S = Q . K^T (3 passes hi/lo), 64 q-rows x 32 k-cols ----
        float s[4][4];
#pragma unroll
        for (int nt = 0; nt < 4; nt++)
#pragma unroll
            for (int e = 0; e < 4; e++) s[nt][e] = 0.0f;

#pragma unroll
        for (int ks = 0; ks < 8; ks++) {
#pragma unroll
            for (int nt2 = 0; nt2 < 2; nt2++) {
                uint32_t kh[4], kl[4];
                ldsm_x4(kh, skhi + (nt2 * 16) * FPB + ks * 32 + a_off);
                ldsm_x4(kl, sklo + (nt2 * 16) * FPB + ks * 32 + a_off);
                uint32_t bh0[2] = {kh[0], kh[2]}, bh1[2] = {kh[1], kh[3]};
                uint32_t bl0[2] = {kl[0], kl[2]}, bl1[2] = {kl[1], kl[3]};
                mma16816(s[2 * nt2],     qfh[ks], bh0);
                mma16816(s[2 * nt2 + 1], qfh[ks], bh1);
                mma16816(s[2 * nt2],     qfh[ks], bl0);
                mma16816(s[2 * nt2 + 1], qfh[ks], bl1);
                mma16816(s[2 * nt2],     qfl[ks], bh0);
                mma16816(s[2 * nt2 + 1], qfl[ks], bh1);
            }
        }

        // ---- causal mask (diagonal tiles) ----
        if (k0 + 32 > q0) {
            const int rq = q0 + wid * 16 + (lane >> 2) - k0;
            const int lc = 2 * (lane & 3);
#pragma unroll
            for (int nt = 0; nt < 4; nt++) {
                int ln = nt * 8 + lc;
                if (ln > rq)         s[nt][0] = -1e30f;
                if (ln + 1 > rq)     s[nt][1] = -1e30f;
                if (ln > rq + 8)     s[nt][2] = -1e30f;
                if (ln + 1 > rq + 8) s[nt][3] = -1e30f;
            }
        }

        // ---- online softmax (log2-domain) ----
        float mx0 = -1e30f, mx1 = -1e30f;
#pragma unroll
        for (int nt = 0; nt < 4; nt++) {
            mx0 = fmaxf(mx0, fmaxf(s[nt][0], s[nt][1]));
            mx1 = fmaxf(mx1, fmaxf(s[nt][2], s[nt][3]));
        }
        mx0 = fmaxf(mx0, __shfl_xor_sync(0xffffffffu, mx0, 1));
        mx0 = fmaxf(mx0, __shfl_xor_sync(0xffffffffu, mx0, 2));
        mx1 = fmaxf(mx1, __shfl_xor_sync(0xffffffffu, mx1, 1));
        mx1 = fmaxf(mx1, __shfl_xor_sync(0xffffffffu, mx1, 2));
        const float newm0 = fmaxf(mrow0, mx0);
        const float newm1 = fmaxf(mrow1, mx1);

        float rs0 = 0.0f, rs1 = 0.0f;
#pragma unroll
        for (int nt = 0; nt < 4; nt++) {
            s[nt][0] = fexp2(s[nt][0] - newm0);
            s[nt][1] = fexp2(s[nt][1] - newm0);
            s[nt][2] = fexp2(s[nt][2] - newm1);
            s[nt][3] = fexp2(s[nt][3] - newm1);
            rs0 += s[nt][0] + s[nt][1];
            rs1 += s[nt][2] + s[nt][3];
        }
        rs0 += __shfl_xor_sync(0xffffffffu, rs0, 1);
        rs0 += __shfl_xor_sync(0xffffffffu, rs0, 2);
        rs1 += __shfl_xor_sync(0xffffffffu, rs1, 1);
        rs1 += __shfl_xor_sync(0xffffffffu, rs1, 2);

        const float al0 = fexp2(mrow0 - newm0);
        const float al1 = fexp2(mrow1 - newm1);
        lrow0 = lrow0 * al0 + rs0;
        lrow1 = lrow1 * al1 + rs1;
        mrow0 = newm0;
        mrow1 = newm1;
#pragma unroll
        for (int nt = 0; nt < 16; nt++) {
            o[nt][0] *= al0; o[nt][1] *= al0;
            o[nt][2] *= al1; o[nt][3] *= al1;
        }

        // ---- O += P . V  (P hi/lo in registers, V hi/lo in smem; 3 passes) ----
#pragma unroll
        for (int t = 0; t < 2; t++) {
            float p00 = s[2 * t][0], p01 = s[2 * t][1];
            float p02 = s[2 * t][2], p03 = s[2 * t][3];
            float p10 = s[2 * t + 1][0], p11 = s[2 * t + 1][1];
            float p12 = s[2 * t + 1][2], p13 = s[2 * t + 1][3];
            uint32_t aph[4], apl[4];
            aph[0] = packbf(p00, p01);
            aph[1] = packbf(p02, p03);
            aph[2] = packbf(p10, p11);
            aph[3] = packbf(p12, p13);
            {
                __nv_bfloat162* hp;
                hp = (__nv_bfloat162*)&aph[0];
                apl[0] = packbf(p00 - __bfloat162float(hp->x), p01 - __bfloat162float(hp->y));
                hp = (__nv_bfloat162*)&aph[1];
                apl[1] = packbf(p02 - __bfloat162float(hp->x), p03 - __bfloat162float(hp->y));
                hp = (__nv_bfloat162*)&aph[2];
                apl[2] = packbf(p10 - __bfloat162float(hp->x), p11 - __bfloat162float(hp->y));
                hp = (__nv_bfloat162*)&aph[3];
                apl[3] = packbf(p12 - __bfloat162float(hp->x), p13 - __bfloat162float(hp->y));
            }
#pragma unroll
            for (int nt2 = 0; nt2 < 8; nt2++) {
                uint32_t vh[4], vl[4];
                ldsm_x4_t(vh, svhi + (t * 16) * FPB + nt2 * 32 + a_off);
                ldsm_x4_t(vl, svlo + (t * 16) * FPB + nt2 * 32 + a_off);
                uint32_t bh0[2] = {vh[0], vh[1]}, bh1[2] = {vh[2], vh[3]};
                uint32_t bl0[2] = {vl[0], vl[1]}, bl1[2] = {vl[2], vl[3]};
                mma16816(o[2 * nt2],     aph, bh0);
                mma16816(o[2 * nt2 + 1], aph, bh1);
                mma16816(o[2 * nt2],     aph, bl0);
                mma16816(o[2 * nt2 + 1], aph, bl1);
                mma16816(o[2 * nt2],     apl, bh0);
                mma16816(o[2 * nt2 + 1], apl, bh1);
            }
        }

        __syncthreads();               // done reading buffer (j & 1)
        if (j + 2 < ntiles) {
            issue_kv(j + 2);
            CP_COMMIT();
        }
    }

    // ---- epilogue: normalize, split to hi/lo bf16, write ----
    const float invl0 = 1.0f / lrow0;
    const float invl1 = 1.0f / lrow1;
    const int grow = b * SEQ + q0 + wid * 16 + (lane >> 2);
    const size_t cbase = (size_t)grow * HIDDEN + h * HD + 2 * (lane & 3);
#pragma unroll
    for (int nt = 0; nt < 16; nt++) {
        float v0 = o[nt][0] * invl0, v1 = o[nt][1] * invl0;
        float v2 = o[nt][2] * invl1, v3 = o[nt][3] * invl1;
        uint32_t h01 = packbf(v0, v1);
        uint32_t h23 = packbf(v2, v3);
        __nv_bfloat162* hp01 = (__nv_bfloat162*)&h01;
        __nv_bfloat162* hp23 = (__nv_bfloat162*)&h23;
        uint32_t l01 = packbf(v0 - __bfloat162float(hp01->x),
                              v1 - __bfloat162float(hp01->y));
        uint32_t l23 = packbf(v2 - __bfloat162float(hp23->x),
                              v3 - __bfloat162float(hp23->y));
        *(uint32_t*)(Ohi + cbase + nt * 8) = h01;
        *(uint32_t*)(Olo + cbase + nt * 8) = l01;
        *(uint32_t*)(Ohi + cbase + (size_t)8 * HIDDEN + nt * 8) = h23;
        *(uint32_t*)(Olo + cbase + (size_t)8 * HIDDEN + nt * 8) = l23;
    }
}

// ---------------- launch ----------------
extern "C" void kernel_launch(void* const* d_in, const int* in_sizes, int n_in,
                              void* d_out, int out_size)
{
    const float* x  = (const float*)d_in[0];
    const float* wq = (const float*)d_in[1];
    const float* wk = (const float*)d_in[2];
    const float* wv = (const float*)d_in[3];
    const float* wo = (const float*)d_in[4];
    float* out = (float*)d_out;

    float2* ropep;
    float *qp, *kp, *vp;
    __nv_bfloat16 *xhi, *xlo, *ahi, *alo, *khi, *klo, *vhi, *vlo;
    __nv_bfloat16 *wqhi, *wqlo, *wkhi, *wklo, *wvhi, *wvlo, *wohi, *wolo;
    cudaGetSymbolAddress((void**)&ropep, g_rope);
    cudaGetSymbolAddress((void**)&qp, g_q);
    cudaGetSymbolAddress((void**)&kp, g_k);
    cudaGetSymbolAddress((void**)&vp, g_v);
    cudaGetSymbolAddress((void**)&xhi, g_xhi);
    cudaGetSymbolAddress((void**)&xlo, g_xlo);
    cudaGetSymbolAddress((void**)&ahi, g_ahi);
    cudaGetSymbolAddress((void**)&alo, g_alo);
    cudaGetSymbolAddress((void**)&khi, g_khi);
    cudaGetSymbolAddress((void**)&klo, g_klo);
    cudaGetSymbolAddress((void**)&vhi, g_vhi);
    cudaGetSymbolAddress((void**)&vlo, g_vlo);
    cudaGetSymbolAddress((void**)&wqhi, g_wqhi);
    cudaGetSymbolAddress((void**)&wqlo, g_wqlo);
    cudaGetSymbolAddress((void**)&wkhi, g_wkhi);
    cudaGetSymbolAddress((void**)&wklo, g_wklo);
    cudaGetSymbolAddress((void**)&wvhi, g_wvhi);
    cudaGetSymbolAddress((void**)&wvlo, g_wvlo);
    cudaGetSymbolAddress((void**)&wohi, g_wohi);
    cudaGetSymbolAddress((void**)&wolo, g_wolo);

    cudaFuncSetAttribute(gemm_mma,
                         cudaFuncAttributeMaxDynamicSharedMemorySize, GSMEM);
    cudaFuncSetAttribute(flash_mma,
                         cudaFuncAttributeMaxDynamicSharedMemorySize, FLASH_SMEM_B);

    const int n4x = MROWS * KDIM / 4;

    GemmProb pq = {wqhi, wqlo, qp, HIDDEN};
    GemmProb pk = {wkhi, wklo, kp, KVW};
    GemmProb pv = {wvhi, wvlo, vp, KVW};
    GemmProb po = {wohi, wolo, out, HIDDEN};

    // rope table + input split + Q/K/V weight splits
    rope_table<<<SEQ * 64 / 256, 256>>>(ropep);
    split_f32<<<(n4x + 255) / 256, 256>>>(x, xhi, xlo, n4x);
    splitT<<<dim3(HIDDEN / 32, KDIM / 32), dim3(32, 8)>>>(wq, wqhi, wqlo, HIDDEN);
    splitT<<<dim3(KVW / 32, KDIM / 32), dim3(32, 8)>>>(wk, wkhi, wklo, KVW);
    splitT<<<dim3(KVW / 32, KDIM / 32), dim3(32, 8)>>>(wv, wvhi, wvlo, KVW);

    // fused Q+K+V projection, grid.x = 16 + 4 + 4
    gemm_mma<<<dim3(24, MROWS / 128), 256, GSMEM>>>(xhi, xlo, pq, pk, pv, 16, 20);

    // fused glue (rope-q + rope-k + v-split), table-based
    glue_kernel<<<RQ_BLOCKS + RK_BLOCKS + VS_BLOCKS, 256>>>(
        qp, kp, vp, ropep, xhi, xlo, khi, klo, vhi, vlo);

    // causal flash attention, occupancy-2 variant (64-row q tiles)
    flash_mma<<<dim3(SEQ / 64, NHEADS, BATCH), 128, FLASH_SMEM_B>>>(
        xhi, xlo, khi, klo, vhi, vlo, ahi, alo);

    // wo split (deferred) + output projection
    splitT<<<dim3(HIDDEN / 32, KDIM / 32), dim3(32, 8)>>>(wo, wohi, wolo, HIDDEN);
    gemm_mma<<<dim3(16, MROWS / 128), 256, GSMEM>>>(ahi, alo, po, po, po, 16, 16);
}

// round 17
// speedup vs baseline: 1.0394x; 1.0075x over previous
#include <cuda_runtime.h>
#include <cuda_bf16.h>
#include <stdint.h>
#include <math.h>

#define HIDDEN 2048
#define NHEADS 16
#define NKV 4
#define HD 128
#define SEQ 2048
#define BATCH 2
#define MROWS (BATCH * SEQ)   // 4096
#define KVW (NKV * HD)        // 512
#define KDIM 2048
// 1/sqrt(128) * log2(e)  (exp2-based softmax)
#define QSCALE_L2E 0.1275174500772518f

// ---------------- scratch (no allocations allowed) ----------------
__device__ __align__(128) float2 g_rope[SEQ * 64];
__device__ __align__(128) float g_q[MROWS * HIDDEN];
__device__ __align__(128) float g_k[MROWS * KVW];
__device__ __align__(128) float g_v[MROWS * KVW];
__device__ __align__(128) __nv_bfloat16 g_xhi[MROWS * KDIM];
__device__ __align__(128) __nv_bfloat16 g_xlo[MROWS * KDIM];
__device__ __align__(128) __nv_bfloat16 g_ahi[MROWS * KDIM];
__device__ __align__(128) __nv_bfloat16 g_alo[MROWS * KDIM];
__device__ __align__(128) __nv_bfloat16 g_khi[MROWS * KVW];
__device__ __align__(128) __nv_bfloat16 g_klo[MROWS * KVW];
__device__ __align__(128) __nv_bfloat16 g_vhi[MROWS * KVW];
__device__ __align__(128) __nv_bfloat16 g_vlo[MROWS * KVW];
__device__ __align__(128) __nv_bfloat16 g_wqhi[HIDDEN * KDIM];  // transposed [N][K]
__device__ __align__(128) __nv_bfloat16 g_wqlo[HIDDEN * KDIM];
__device__ __align__(128) __nv_bfloat16 g_wkhi[KVW * KDIM];
__device__ __align__(128) __nv_bfloat16 g_wklo[KVW * KDIM];
__device__ __align__(128) __nv_bfloat16 g_wvhi[KVW * KDIM];
__device__ __align__(128) __nv_bfloat16 g_wvlo[KVW * KDIM];
__device__ __align__(128) __nv_bfloat16 g_wohi[HIDDEN * KDIM];
__device__ __align__(128) __nv_bfloat16 g_wolo[HIDDEN * KDIM];

// ================= helpers =================
__device__ __forceinline__ uint32_t smem_u32(const void* p) {
    uint32_t a;
    asm("{ .reg .u64 t; cvta.to.shared.u64 t, %1; cvt.u32.u64 %0, t; }"
        : "=r"(a) : "l"(p));
    return a;
}
#define CP_ASYNC16(dst, src) \
    asm volatile("cp.async.cg.shared.global [%0], [%1], 16;" :: "r"(dst), "l"(src) : "memory")
#define CP_COMMIT() asm volatile("cp.async.commit_group;" ::: "memory")
#define CP_WAIT1()  asm volatile("cp.async.wait_group 1;" ::: "memory")
#define CP_WAIT0()  asm volatile("cp.async.wait_group 0;" ::: "memory")

__device__ __forceinline__ void ldsm_x4(uint32_t* r, uint32_t addr) {
    asm volatile("ldmatrix.sync.aligned.m8n8.x4.shared.b16 {%0,%1,%2,%3}, [%4];"
                 : "=r"(r[0]), "=r"(r[1]), "=r"(r[2]), "=r"(r[3]) : "r"(addr));
}
__device__ __forceinline__ void ldsm_x4_t(uint32_t* r, uint32_t addr) {
    asm volatile("ldmatrix.sync.aligned.m8n8.x4.trans.shared.b16 {%0,%1,%2,%3}, [%4];"
                 : "=r"(r[0]), "=r"(r[1]), "=r"(r[2]), "=r"(r[3]) : "r"(addr));
}
__device__ __forceinline__ void mma16816(float* d, const uint32_t* a, const uint32_t* b) {
    asm volatile("mma.sync.aligned.m16n8k16.row.col.f32.bf16.bf16.f32 "
                 "{%0,%1,%2,%3}, {%4,%5,%6,%7}, {%8,%9}, {%0,%1,%2,%3};"
                 : "+f"(d[0]), "+f"(d[1]), "+f"(d[2]), "+f"(d[3])
                 : "r"(a[0]), "r"(a[1]), "r"(a[2]), "r"(a[3]), "r"(b[0]), "r"(b[1]));
}
__device__ __forceinline__ uint32_t packbf(float x, float y) {
    __nv_bfloat162 t;
    t.x = __float2bfloat16_rn(x);
    t.y = __float2bfloat16_rn(y);
    return *(uint32_t*)&t;
}
__device__ __forceinline__ float fexp2(float x) {
    float y;
    asm("ex2.approx.f32 %0, %1;" : "=f"(y) : "f"(x));
    return y;
}

// ================= RoPE cos/sin table =================
__global__ void rope_table(float2* __restrict__ tab)
{
    int idx = blockIdx.x * blockDim.x + threadIdx.x;   // SEQ*64
    int s = idx >> 6;
    int d = idx & 63;
    float inv = exp2f(-(float)d * (13.287712379549449f / 64.0f));
    float ang = (float)s * inv;
    float sn, cs;
    sincosf(ang, &sn, &cs);
    tab[idx] = make_float2(cs, sn);
}

// ================= fp32 -> bf16 hi/lo split =================
__global__ void split_f32(const float* __restrict__ x,
                          __nv_bfloat16* __restrict__ hi,
                          __nv_bfloat16* __restrict__ lo, int n4)
{
    int i = blockIdx.x * blockDim.x + threadIdx.x;
    if (i >= n4) return;
    float4 v = ((const float4*)x)[i];
    __nv_bfloat16 h0 = __float2bfloat16(v.x);
    __nv_bfloat16 h1 = __float2bfloat16(v.y);
    __nv_bfloat16 h2 = __float2bfloat16(v.z);
    __nv_bfloat16 h3 = __float2bfloat16(v.w);
    __nv_bfloat16 l0 = __float2bfloat16(v.x - __bfloat162float(h0));
    __nv_bfloat16 l1 = __float2bfloat16(v.y - __bfloat162float(h1));
    __nv_bfloat16 l2 = __float2bfloat16(v.z - __bfloat162float(h2));
    __nv_bfloat16 l3 = __float2bfloat16(v.w - __bfloat162float(h3));
    ((__nv_bfloat162*)hi)[2 * i]     = __nv_bfloat162(h0, h1);
    ((__nv_bfloat162*)hi)[2 * i + 1] = __nv_bfloat162(h2, h3);
    ((__nv_bfloat162*)lo)[2 * i]     = __nv_bfloat162(l0, l1);
    ((__nv_bfloat162*)lo)[2 * i + 1] = __nv_bfloat162(l2, l3);
}

// transpose + split: W [KDIM][Nw] fp32 -> hiT/loT [Nw][KDIM] bf16
__global__ void splitT(const float* __restrict__ W,
                       __nv_bfloat16* __restrict__ hiT,
                       __nv_bfloat16* __restrict__ loT, int Nw)
{
    __shared__ float t[32][33];
    int n0 = blockIdx.x * 32, k0 = blockIdx.y * 32;
    int tx = threadIdx.x, ty = threadIdx.y;
#pragma unroll
    for (int i = 0; i < 32; i += 8)
        t[ty + i][tx] = W[(size_t)(k0 + ty + i) * Nw + n0 + tx];
    __syncthreads();
#pragma unroll
    for (int i = 0; i < 32; i += 8) {
        float v = t[tx][ty + i];
        __nv_bfloat16 h = __float2bfloat16(v);
        size_t o = (size_t)(n0 + ty + i) * KDIM + k0 + tx;
        hiT[o] = h;
        loT[o] = __float2bfloat16(v - __bfloat162float(h));
    }
}

// ---------------- fused glue: rope-q + rope-k + v-split (table-based) ---------
#define RQ_BLOCKS (MROWS * NHEADS * 64 / 256)       // 16384
#define RK_BLOCKS (MROWS * NKV * 64 / 256)          // 4096
#define VS_BLOCKS (MROWS * KVW / 4 / 256)           // 2048

__device__ __forceinline__ void rope_one(const float* __restrict__ x,
                                         const float2* __restrict__ tab,
                                         __nv_bfloat16* __restrict__ hi,
                                         __nv_bfloat16* __restrict__ lo,
                                         int idx, int heads, float scale)
{
    int d = idx & 63;
    int t = idx >> 6;
    int h = t % heads;
    int m = t / heads;
    int s = m & (SEQ - 1);

    float2 csn = __ldg(tab + s * 64 + d);

    size_t base = (size_t)m * (heads * 128) + h * 128 + d;
    float xlo = x[base];
    float xhi = x[base + 64];
    float y0 = (xlo * csn.x - xhi * csn.y) * scale;
    float y1 = (xhi * csn.x + xlo * csn.y) * scale;

    __nv_bfloat16 h0 = __float2bfloat16(y0);
    __nv_bfloat16 h1 = __float2bfloat16(y1);
    hi[base]      = h0;
    hi[base + 64] = h1;
    lo[base]      = __float2bfloat16(y0 - __bfloat162float(h0));
    lo[base + 64] = __float2bfloat16(y1 - __bfloat162float(h1));
}

__global__ void glue_kernel(const float* __restrict__ q,
                            const float* __restrict__ k,
                            const float* __restrict__ v,
                            const float2* __restrict__ tab,
                            __nv_bfloat16* __restrict__ qhi, __nv_bfloat16* __restrict__ qlo,
                            __nv_bfloat16* __restrict__ khi, __nv_bfloat16* __restrict__ klo,
                            __nv_bfloat16* __restrict__ vhi, __nv_bfloat16* __restrict__ vlo)
{
    int bx = blockIdx.x;
    if (bx < RQ_BLOCKS) {
        rope_one(q, tab, qhi, qlo, bx * 256 + threadIdx.x, NHEADS, QSCALE_L2E);
    } else if (bx < RQ_BLOCKS + RK_BLOCKS) {
        rope_one(k, tab, khi, klo, (bx - RQ_BLOCKS) * 256 + threadIdx.x, NKV, 1.0f);
    } else {
        int i = (bx - RQ_BLOCKS - RK_BLOCKS) * 256 + threadIdx.x;
        float4 vv = ((const float4*)v)[i];
        __nv_bfloat16 h0 = __float2bfloat16(vv.x);
        __nv_bfloat16 h1 = __float2bfloat16(vv.y);
        __nv_bfloat16 h2 = __float2bfloat16(vv.z);
        __nv_bfloat16 h3 = __float2bfloat16(vv.w);
        ((__nv_bfloat162*)vhi)[2 * i]     = __nv_bfloat162(h0, h1);
        ((__nv_bfloat162*)vhi)[2 * i + 1] = __nv_bfloat162(h2, h3);
        ((__nv_bfloat162*)vlo)[2 * i]     = __nv_bfloat162(
            __float2bfloat16(vv.x - __bfloat162float(h0)),
            __float2bfloat16(vv.y - __bfloat162float(h1)));
        ((__nv_bfloat162*)vlo)[2 * i + 1] = __nv_bfloat162(
            __float2bfloat16(vv.z - __bfloat162float(h2)),
            __float2bfloat16(vv.w - __bfloat162float(h3)));
    }
}

// ================= tensor-core GEMM via mma.sync, bf16x3 split =================
// Up to 3 fused (B, C) problem sets along blockIdx.x (range-selected).
#define BK 32
#define APITCH_B 80
#define TILE_B (128 * APITCH_B)
#define BUF_B (4 * TILE_B)
#define GSMEM (2 * BUF_B)
#define NCHG (KDIM / BK)

struct GemmProb {
    const __nv_bfloat16* Bhi;
    const __nv_bfloat16* Blo;
    float* C;
    int N;
};

__global__ __launch_bounds__(256, 2)
void gemm_mma(const __nv_bfloat16* __restrict__ Ahi,
              const __nv_bfloat16* __restrict__ Alo,
              GemmProb p0, GemmProb p1, GemmProb p2, int c0, int c1)
{
    extern __shared__ char smem[];
    const uint32_t sb = smem_u32(smem);
    const int tid = threadIdx.x;
    const int wid = tid >> 5, lane = tid & 31;
    const int wm = wid >> 2, wn = wid & 3;
    const int m0 = blockIdx.y << 7;

    int bx = blockIdx.x;
    const GemmProb* p;
    if (bx < c0)       { p = &p0; }
    else if (bx < c1)  { p = &p1; bx -= c0; }
    else               { p = &p2; bx -= c1; }
    const int n0 = bx << 7;
    const __nv_bfloat16* Bhi = p->Bhi;
    const __nv_bfloat16* Blo = p->Blo;
    float* C = p->C;
    const int N = p->N;

    const char* gsrc[4];
    gsrc[0] = (const char*)(Ahi + (size_t)m0 * KDIM);
    gsrc[1] = (const char*)(Alo + (size_t)m0 * KDIM);
    gsrc[2] = (const char*)(Bhi + (size_t)n0 * KDIM);
    gsrc[3] = (const char*)(Blo + (size_t)n0 * KDIM);

    const int r0 = tid >> 2, s0 = tid & 3;
    const int r1 = (tid + 256) >> 2, s1 = tid & 3;

    auto load_chunk = [&](int c) {
        const int buf = c & 1;
#pragma unroll
        for (int t = 0; t < 4; t++) {
            const char* gb = gsrc[t] + (size_t)c * (BK * 2);
            uint32_t st = sb + buf * BUF_B + t * TILE_B;
            CP_ASYNC16(st + r0 * APITCH_B + s0 * 16,
                       gb + (size_t)r0 * (KDIM * 2) + s0 * 16);
            CP_ASYNC16(st + r1 * APITCH_B + s1 * 16,
                       gb + (size_t)r1 * (KDIM * 2) + s1 * 16);
        }
    };

    float acc[4][4][4];
#pragma unroll
    for (int i = 0; i < 4; i++)
#pragma unroll
        for (int j = 0; j < 4; j++)
#pragma unroll
            for (int e = 0; e < 4; e++) acc[i][j][e] = 0.0f;

    const uint32_t a_off = (uint32_t)((lane & 15) * APITCH_B + (lane >> 4) * 16);
    const int bg = lane >> 3;
    const uint32_t b_off = (uint32_t)(((bg >> 1) * 8 + (lane & 7)) * APITCH_B + (bg & 1) * 16);

    load_chunk(0);
    CP_COMMIT();

    for (int c = 0; c < NCHG; ++c) {
        if (c + 1 < NCHG) load_chunk(c + 1);
        CP_COMMIT();
        CP_WAIT1();
        __syncthreads();

        const uint32_t base = sb + (c & 1) * BUF_B;
        const uint32_t sAhi = base + 0 * TILE_B + (wm * 64) * APITCH_B;
        const uint32_t sAlo = base + 1 * TILE_B + (wm * 64) * APITCH_B;
        const uint32_t sBhi = base + 2 * TILE_B + (wn * 32) * APITCH_B;
        const uint32_t sBlo = base + 3 * TILE_B + (wn * 32) * APITCH_B;
#pragma unroll
        for (int ks = 0; ks < 2; ks++) {
            const uint32_t koff = ks * 32;
            uint32_t ahi[4][4], bh[4][2];
#pragma unroll
            for (int fm = 0; fm < 4; fm++)
                ldsm_x4(ahi[fm], sAhi + fm * 16 * APITCH_B + koff + a_off);
#pragma unroll
            for (int f2 = 0; f2 < 2; f2++) {
                uint32_t r[4];
                ldsm_x4(r, sBhi + f2 * 16 * APITCH_B + koff + b_off);
                bh[2 * f2][0] = r[0]; bh[2 * f2][1] = r[1];
                bh[2 * f2 + 1][0] = r[2]; bh[2 * f2 + 1][1] = r[3];
            }
            // ahi x bhi
#pragma unroll
            for (int fm = 0; fm < 4; fm++)
#pragma unroll
                for (int fn = 0; fn < 4; fn++)
                    mma16816(acc[fm][fn], ahi[fm], bh[fn]);
            {
                uint32_t bl[4][2];
#pragma unroll
                for (int f2 = 0; f2 < 2; f2++) {
                    uint32_t r[4];
                    ldsm_x4(r, sBlo + f2 * 16 * APITCH_B + koff + b_off);
                    bl[2 * f2][0] = r[0]; bl[2 * f2][1] = r[1];
                    bl[2 * f2 + 1][0] = r[2]; bl[2 * f2 + 1][1] = r[3];
                }
                // ahi x blo
#pragma unroll
                for (int fm = 0; fm < 4; fm++)
#pragma unroll
                    for (int fn = 0; fn < 4; fn++)
                        mma16816(acc[fm][fn], ahi[fm], bl[fn]);
            }
            // alo x bhi (ahi registers dead; reuse)
            uint32_t alo[4][4];
#pragma unroll
            for (int fm = 0; fm < 4; fm++)
                ldsm_x4(alo[fm], sAlo + fm * 16 * APITCH_B + koff + a_off);
#pragma unroll
            for (int fm = 0; fm < 4; fm++)
#pragma unroll
                for (int fn = 0; fn < 4; fn++)
                    mma16816(acc[fm][fn], alo[fm], bh[fn]);
        }
        __syncthreads();
    }

    const int erow = lane >> 2;
    const int ecol = (lane & 3) * 2;
#pragma unroll
    for (int fm = 0; fm < 4; fm++) {
#pragma unroll
        for (int fn = 0; fn < 4; fn++) {
            int row = m0 + wm * 64 + fm * 16 + erow;
            int col = n0 + wn * 32 + fn * 8 + ecol;
            *(float2*)(C + (size_t)row * N + col) =
                make_float2(acc[fm][fn][0], acc[fm][fn][1]);
            *(float2*)(C + (size_t)(row + 8) * N + col) =
                make_float2(acc[fm][fn][2], acc[fm][fn][3]);
        }
    }
}

// ================= tensor-core flash attention (causal, GQA) =================
// Occupancy-2 variant: 128 threads (4 warps), q-tile 64 rows, KV step 64 cols,
// single KV buffer (cross-CTA overlap hides loads); Q fragments in registers.
#define FPB 272                          // smem row pitch bytes (136 bf16)
#define F_QTILE_B (64 * FPB)             // 17408
#define F_KVTILE_B (64 * FPB)            // 17408
#define SMB_QHI 0
#define SMB_QLO F_QTILE_B
#define SMB_KV  (2 * F_QTILE_B)          // 34816; 1 buf x 4 tiles follows
#define FLASH_SMEM_B (2 * F_QTILE_B + 4 * F_KVTILE_B)  // 104448 -> 2 CTAs/SM

__global__ __launch_bounds__(128, 2)
void flash_mma(const __nv_bfloat16* __restrict__ Qhi,
               const __nv_bfloat16* __restrict__ Qlo,
               const __nv_bfloat16* __restrict__ Khi,
               const __nv_bfloat16* __restrict__ Klo,
               const __nv_bfloat16* __restrict__ Vhi,
               const __nv_bfloat16* __restrict__ Vlo,
               __nv_bfloat16* __restrict__ Ohi,
               __nv_bfloat16* __restrict__ Olo)
{
    extern __shared__ char smem[];
    const uint32_t sb = smem_u32(smem);
    const int tid = threadIdx.x;
    const int wid = tid >> 5, lane = tid & 31;
    const int qt = 31 - (int)blockIdx.x;     // heavy tiles first
    const int h = blockIdx.y, b = blockIdx.z;
    const int g = h >> 2;
    const int q0 = qt << 6;                  // 64-row q tile
    const int ntiles = qt + 1;               // 64-col kv tiles

    const uint32_t a_off = (uint32_t)((lane & 15) * FPB + (lane >> 4) * 16);

    const char* kh_base = (const char*)(Khi + (size_t)(b * SEQ) * KVW + g * HD);
    const char* kl_base = (const char*)(Klo + (size_t)(b * SEQ) * KVW + g * HD);
    const char* vh_base = (const char*)(Vhi + (size_t)(b * SEQ) * KVW + g * HD);
    const char* vl_base = (const char*)(Vlo + (size_t)(b * SEQ) * KVW + g * HD);

    auto issue_kv = [&](int j) {
        const uint32_t dst = sb + SMB_KV;
        const int k0 = j << 6;
        const char* srcs[4] = {kh_base, kl_base, vh_base, vl_base};
#pragma unroll
        for (int t = 0; t < 4; t++) {
#pragma unroll
            for (int i = 0; i < 8; i++) {
                int idx = i * 128 + tid;         // 0..1023
                int row = idx >> 4, c = idx & 15;
                CP_ASYNC16(dst + t * F_KVTILE_B + row * FPB + c * 16,
                           srcs[t] + (size_t)(k0 + row) * (KVW * 2) + c * 16);
            }
        }
    };

    // ---- prologue: Q tiles + first KV tile ----
    {
        const char* qh = (const char*)(Qhi + (size_t)(b * SEQ + q0) * HIDDEN + h * HD);
        const char* ql = (const char*)(Qlo + (size_t)(b * SEQ + q0) * HIDDEN + h * HD);
#pragma unroll
        for (int i = 0; i < 8; i++) {
            int idx = i * 128 + tid;             // 0..1023
            int row = idx >> 4, c = idx & 15;
            CP_ASYNC16(sb + SMB_QHI + row * FPB + c * 16,
                       qh + (size_t)row * (HIDDEN * 2) + c * 16);
            CP_ASYNC16(sb + SMB_QLO + row * FPB + c * 16,
                       ql + (size_t)row * (HIDDEN * 2) + c * 16);
        }
        CP_COMMIT();
    }
    issue_kv(0);
    CP_COMMIT();
    CP_WAIT0();
    __syncthreads();

    // ---- hoist Q fragments into registers (loop-invariant) ----
    uint32_t qfh[8][4], qfl[8][4];
#pragma unroll
    for (int ks = 0; ks < 8; ks++) {
        ldsm_x4(qfh[ks], sb + SMB_QHI + (wid * 16) * FPB + ks * 32 + a_off);
        ldsm_x4(qfl[ks], sb + SMB_QLO + (wid * 16) * FPB + ks * 32 + a_off);
    }

    float o[16][4];
#pragma unroll
    for (int nt = 0; nt < 16; nt++)
#pragma unroll
        for (int e = 0; e < 4; e++) o[nt][e] = 0.0f;
    float mrow0 = -INFINITY, mrow1 = -INFINITY, lrow0 = 0.0f, lrow1 = 0.0f;

    for (int j = 0; j < ntiles; j++) {
        const uint32_t skhi = sb + SMB_KV;
        const uint32_t sklo = skhi + F_KVTILE_B;
        const uint32_t svhi = skhi + 2 * F_KVTILE_B;
        const uint32_t svlo = skhi + 3 * F_KVTILE_B;
        const int k0 = j << 6;

        // ---- S = Q . K^T (3 passes hi/lo), 64 q-rows x 64 k-cols ----
        float s[8][4];
#pragma unroll
        for (int nt = 0; nt < 8; nt++)
#pragma unroll
            for (int e = 0; e < 4; e++) s[nt][e] = 0.0f;

#pragma unroll
        for (int ks = 0; ks < 8; ks++) {
#pragma unroll
            for (int nt2 = 0; nt2 < 4; nt2++) {
                uint32_t kh[4], kl[4];
                ldsm_x4(kh, skhi + (nt2 * 16) * FPB + ks * 32 + a_off);
                ldsm_x4(kl, sklo + (nt2 * 16) * FPB + ks * 32 + a_off);
                uint32_t bh0[2] = {kh[0], kh[2]}, bh1[2] = {kh[1], kh[3]};
                uint32_t bl0[2] = {kl[0], kl[2]}, bl1[2] = {kl[1], kl[3]};
                mma16816(s[2 * nt2],     qfh[ks], bh0);
                mma16816(s[2 * nt2 + 1], qfh[ks], bh1);
                mma16816(s[2 * nt2],     qfh[ks], bl0);
                mma16816(s[2 * nt2 + 1], qfh[ks], bl1);
                mma16816(s[2 * nt2],     qfl[ks], bh0);
                mma16816(s[2 * nt2 + 1], qfl[ks], bh1);
            }
        }

        // ---- causal mask (diagonal tiles) ----
        if (k0 + 64 > q0) {
            const int rq = q0 + wid * 16 + (lane >> 2) - k0;
            const int lc = 2 * (lane & 3);
#pragma unroll
            for (int nt = 0; nt < 8; nt++) {
                int ln = nt * 8 + lc;
                if (ln > rq)         s[nt][0] = -1e30f;
                if (ln + 1 > rq)     s[nt][1] = -1e30f;
                if (ln > rq + 8)     s[nt][2] = -1e30f;
                if (ln + 1 > rq + 8) s[nt][3] = -1e30f;
            }
        }

        // ---- online softmax (log2-domain) ----
        float mx0 = -1e30f, mx1 = -1e30f;
#pragma unroll
        for (int nt = 0; nt < 8; nt++) {
            mx0 = fmaxf(mx0, fmaxf(s[nt][0], s[nt][1]));
            mx1 = fmaxf(mx1, fmaxf(s[nt][2], s[nt][3]));
        }
        mx0 = fmaxf(mx0, __shfl_xor_sync(0xffffffffu, mx0, 1));
        mx0 = fmaxf(mx0, __shfl_xor_sync(0xffffffffu, mx0, 2));
        mx1 = fmaxf(mx1, __shfl_xor_sync(0xffffffffu, mx1, 1));
        mx1 = fmaxf(mx1, __shfl_xor_sync(0xffffffffu, mx1, 2));
        const float newm0 = fmaxf(mrow0, mx0);
        const float newm1 = fmaxf(mrow1, mx1);

        float rs0 = 0.0f, rs1 = 0.0f;
#pragma unroll
        for (int nt = 0; nt < 8; nt++) {
            s[nt][0] = fexp2(s[nt][0] - newm0);
            s[nt][1] = fexp2(s[nt][1] - newm0);
            s[nt][2] = fexp2(s[nt][2] - newm1);
            s[nt][3] = fexp2(s[nt][3] - newm1);
            rs0 += s[nt][0] + s[nt][1];
            rs1 += s[nt][2] + s[nt][3];
        }
        rs0 += __shfl_xor_sync(0xffffffffu, rs0, 1);
        rs0 += __shfl_xor_sync(0xffffffffu, rs0, 2);
        rs1 += __shfl_xor_sync(0xffffffffu, rs1, 1);
        rs1 += __shfl_xor_sync(0xffffffffu, rs1, 2);

        const float al0 = fexp2(mrow0 - newm0);
        const float al1 = fexp2(mrow1 - newm1);
        lrow0 = lrow0 * al0 + rs0;
        lrow1 = lrow1 * al1 + rs1;
        mrow0 = newm0;
        mrow1 = newm1;
#pragma unroll
        for (int nt = 0; nt < 16; nt++) {
            o[nt][0] *= al0; o[nt][1] *= al0;
            o[nt][2] *= al1; o[nt][3] *= al1;
        }

        // ---- O += P . V  (P hi/lo in registers, V hi/lo in smem; 3 passes) ----
#pragma unroll
        for (int t = 0; t < 4; t++) {
            float p00 = s[2 * t][0], p01 = s[2 * t][1];
            float p02 = s[2 * t][2], p03 = s[2 * t][3];
            float p10 = s[2 * t + 1][0], p11 = s[2 * t + 1][1];
            float p12 = s[2 * t + 1][2], p13 = s[2 * t + 1][3];
            uint32_t aph[4], apl[4];
            aph[0] = packbf(p00, p01);
            aph[1] = packbf(p02, p03);
            aph[2] = packbf(p10, p11);
            aph[3] = packbf(p12, p13);
            {
                __nv_bfloat162* hp;
                hp = (__nv_bfloat162*)&aph[0];
                apl[0] = packbf(p00 - __bfloat162float(hp->x), p01 - __bfloat162float(hp->y));
                hp = (__nv_bfloat162*)&aph[1];
                apl[1] = packbf(p02 - __bfloat162float(hp->x), p03 - __bfloat162float(hp->y));
                hp = (__nv_bfloat162*)&aph[2];
                apl[2] = packbf(p10 - __bfloat162float(hp->x), p11 - __bfloat162float(hp->y));
                hp = (__nv_bfloat162*)&aph[3];
                apl[3] = packbf(p12 - __bfloat162float(hp->x), p13 - __bfloat162float(hp->y));
            }
#pragma unroll
            for (int nt2 = 0; nt2 < 8; nt2++) {
                uint32_t vh[4], vl[4];
                ldsm_x4_t(vh, svhi + (t * 16) * FPB + nt2 * 32 + a_off);
                ldsm_x4_t(vl, svlo + (t * 16) * FPB + nt2 * 32 + a_off);
                uint32_t bh0[2] = {vh[0], vh[1]}, bh1[2] = {vh[2], vh[3]};
                uint32_t bl0[2] = {vl[0], vl[1]}, bl1[2] = {vl[2], vl[3]};
                mma16816(o[2 * nt2],     aph, bh0);
                mma16816(o[2 * nt2 + 1], aph, bh1);
                mma16816(o[2 * nt2],     aph, bl0);
                mma16816(o[2 * nt2 + 1], aph, bl1);
                mma16816(o[2 * nt2],     apl, bh0);
                mma16816(o[2 * nt2 + 1], apl, bh1);
            }
        }

        // ---- load next KV tile (single buffer; co-resident CTA hides) ----
        __syncthreads();               // all warps done reading buffer
        if (j + 1 < ntiles) {
            issue_kv(j + 1);
            CP_COMMIT();
            CP_WAIT0();
            __syncthreads();
        }
    }

    // ---- epilogue: normalize, split to hi/lo bf16, write ----
    const float invl0 = 1.0f / lrow0;
    const float invl1 = 1.0f / lrow1;
    const int grow = b * SEQ + q0 + wid * 16 + (lane >> 2);
    const size_t cbase = (size_t)grow * HIDDEN + h * HD + 2 * (lane & 3);
#pragma unroll
    for (int nt = 0; nt < 16; nt++) {
        float v0 = o[nt][0] * invl0, v1 = o[nt][1] * invl0;
        float v2 = o[nt][2] * invl1, v3 = o[nt][3] * invl1;
        uint32_t h01 = packbf(v0, v1);
        uint32_t h23 = packbf(v2, v3);
        __nv_bfloat162* hp01 = (__nv_bfloat162*)&h01;
        __nv_bfloat162* hp23 = (__nv_bfloat162*)&h23;
        uint32_t l01 = packbf(v0 - __bfloat162float(hp01->x),
                              v1 - __bfloat162float(hp01->y));
        uint32_t l23 = packbf(v2 - __bfloat162float(hp23->x),
                              v3 - __bfloat162float(hp23->y));
        *(uint32_t*)(Ohi + cbase + nt * 8) = h01;
        *(uint32_t*)(Olo + cbase + nt * 8) = l01;
        *(uint32_t*)(Ohi + cbase + (size_t)8 * HIDDEN + nt * 8) = h23;
        *(uint32_t*)(Olo + cbase + (size_t)8 * HIDDEN + nt * 8) = l23;
    }
}

// ---------------- launch ----------------
extern "C" void kernel_launch(void* const* d_in, const int* in_sizes, int n_in,
                              void* d_out, int out_size)
{
    const float* x  = (const float*)d_in[0];
    const float* wq = (const float*)d_in[1];
    const float* wk = (const float*)d_in[2];
    const float* wv = (const float*)d_in[3];
    const float* wo = (const float*)d_in[4];
    float* out = (float*)d_out;

    float2* ropep;
    float *qp, *kp, *vp;
    __nv_bfloat16 *xhi, *xlo, *ahi, *alo, *khi, *klo, *vhi, *vlo;
    __nv_bfloat16 *wqhi, *wqlo, *wkhi, *wklo, *wvhi, *wvlo, *wohi, *wolo;
    cudaGetSymbolAddress((void**)&ropep, g_rope);
    cudaGetSymbolAddress((void**)&qp, g_q);
    cudaGetSymbolAddress((void**)&kp, g_k);
    cudaGetSymbolAddress((void**)&vp, g_v);
    cudaGetSymbolAddress((void**)&xhi, g_xhi);
    cudaGetSymbolAddress((void**)&xlo, g_xlo);
    cudaGetSymbolAddress((void**)&ahi, g_ahi);
    cudaGetSymbolAddress((void**)&alo, g_alo);
    cudaGetSymbolAddress((void**)&khi, g_khi);
    cudaGetSymbolAddress((void**)&klo, g_klo);
    cudaGetSymbolAddress((void**)&vhi, g_vhi);
    cudaGetSymbolAddress((void**)&vlo, g_vlo);
    cudaGetSymbolAddress((void**)&wqhi, g_wqhi);
    cudaGetSymbolAddress((void**)&wqlo, g_wqlo);
    cudaGetSymbolAddress((void**)&wkhi, g_wkhi);
    cudaGetSymbolAddress((void**)&wklo, g_wklo);
    cudaGetSymbolAddress((void**)&wvhi, g_wvhi);
    cudaGetSymbolAddress((void**)&wvlo, g_wvlo);
    cudaGetSymbolAddress((void**)&wohi, g_wohi);
    cudaGetSymbolAddress((void**)&wolo, g_wolo);

    cudaFuncSetAttribute(gemm_mma,
                         cudaFuncAttributeMaxDynamicSharedMemorySize, GSMEM);
    cudaFuncSetAttribute(flash_mma,
                         cudaFuncAttributeMaxDynamicSharedMemorySize, FLASH_SMEM_B);

    const int n4x = MROWS * KDIM / 4;

    GemmProb pq = {wqhi, wqlo, qp, HIDDEN};
    GemmProb pk = {wkhi, wklo, kp, KVW};
    GemmProb pv = {wvhi, wvlo, vp, KVW};
    GemmProb po = {wohi, wolo, out, HIDDEN};

    // rope table + input split + Q/K/V weight splits
    rope_table<<<SEQ * 64 / 256, 256>>>(ropep);
    split_f32<<<(n4x + 255) / 256, 256>>>(x, xhi, xlo, n4x);
    splitT<<<dim3(HIDDEN / 32, KDIM / 32), dim3(32, 8)>>>(wq, wqhi, wqlo, HIDDEN);
    splitT<<<dim3(KVW / 32, KDIM / 32), dim3(32, 8)>>>(wk, wkhi, wklo, KVW);
    splitT<<<dim3(KVW / 32, KDIM / 32), dim3(32, 8)>>>(wv, wvhi, wvlo, KVW);

    // fused Q+K+V projection, grid.x = 16 + 4 + 4
    gemm_mma<<<dim3(24, MROWS / 128), 256, GSMEM>>>(xhi, xlo, pq, pk, pv, 16, 20);

    // fused glue (rope-q + rope-k + v-split), table-based
    glue_kernel<<<RQ_BLOCKS + RK_BLOCKS + VS_BLOCKS, 256>>>(
        qp, kp, vp, ropep, xhi, xlo, khi, klo, vhi, vlo);

    // causal flash attention, occ-2, 64-col KV step, single-buffered
    flash_mma<<<dim3(SEQ / 64, NHEADS, BATCH), 128, FLASH_SMEM_B>>>(
        xhi, xlo, khi, klo, vhi, vlo, ahi, alo);

    // wo split (deferred) + output projection
    splitT<<<dim3(HIDDEN / 32, KDIM / 32), dim3(32, 8)>>>(wo, wohi, wolo, HIDDEN);
    gemm_mma<<<dim3(16, MROWS / 128), 256, GSMEM>>>(ahi, alo, po, po, po, 16, 16);
}